// round 4
// baseline (speedup 1.0000x reference)
#include <cuda_runtime.h>
#include <cstdint>
#include <math.h>

#define BB 8
#define CC 64
#define HH 64
#define WW 64

// ---------------- scratch (static device globals; no allocation) ----------------
__device__ float g_feat[BB*CC*HH*WW];      // [B][C][H][W]
__device__ float g_f1[BB*4096*CC];         // [B][N][C] pooled/transposed features
__device__ float g_f2[BB*1024*CC];
__device__ float g_f4[BB*256*CC];
__device__ float g_o1[BB*CC*4096];         // [B][C][n] attention outputs
__device__ float g_o2[BB*CC*1024];
__device__ float g_o4[BB*CC*256];

__device__ __forceinline__ float tf32r(float v) {   // round-to-nearest tf32
    uint32_t u;
    asm("cvt.rna.tf32.f32 %0, %1;" : "=r"(u) : "f"(v));
    return __uint_as_float(u);
}
__device__ __forceinline__ uint32_t packbf(float lo, float hi) {  // {lo16, hi16}
    uint32_t r;
    asm("cvt.rn.bf16x2.f32 %0, %1, %2;" : "=r"(r) : "f"(hi), "f"(lo));
    return r;
}
__device__ __forceinline__ int islot(int j) { return 2*(j & 3) + (j >> 2); }

// m16n8k8 tf32 MMA, row.col, fp32 accumulate-in-place
__device__ __forceinline__ void mma8(float* d, uint32_t a0, uint32_t a1, uint32_t a2,
                                     uint32_t a3, uint32_t b0, uint32_t b1) {
    asm volatile("mma.sync.aligned.m16n8k8.row.col.f32.tf32.tf32.f32 "
        "{%0,%1,%2,%3}, {%4,%5,%6,%7}, {%8,%9}, {%0,%1,%2,%3};"
        : "+f"(d[0]), "+f"(d[1]), "+f"(d[2]), "+f"(d[3])
        : "r"(a0), "r"(a1), "r"(a2), "r"(a3), "r"(b0), "r"(b1));
}
// m16n8k16 bf16 MMA
__device__ __forceinline__ void mma16(float* d, uint32_t a0, uint32_t a1, uint32_t a2,
                                      uint32_t a3, uint32_t b0, uint32_t b1) {
    asm volatile("mma.sync.aligned.m16n8k16.row.col.f32.bf16.bf16.f32 "
        "{%0,%1,%2,%3}, {%4,%5,%6,%7}, {%8,%9}, {%0,%1,%2,%3};"
        : "+f"(d[0]), "+f"(d[1]), "+f"(d[2]), "+f"(d[3])
        : "r"(a0), "r"(a1), "r"(a2), "r"(a3), "r"(b0), "r"(b1));
}

// ---------------- Stage 1: 3x3 conv + depthwise Laplacian ----------------
__global__ void __launch_bounds__(256) conv_kernel(const float* __restrict__ x,
                                                   const float* __restrict__ w) {
    __shared__ float xs[18][18];
    __shared__ float ws[64][9];
    const int tile = blockIdx.x;
    const int b = blockIdx.y;
    const int y0 = (tile >> 2) << 4;
    const int x0 = (tile & 3) << 4;
    const int tid = threadIdx.x;
    const int px = tid & 15, py = tid >> 4;
    float acc[64];
#pragma unroll
    for (int i = 0; i < 64; i++) acc[i] = 0.f;
    const float* xb = x + b*CC*HH*WW;
    for (int ic = 0; ic < 64; ic++) {
        for (int i = tid; i < 18*18; i += 256) {
            int yy = i / 18, xx = i % 18;
            int gy = y0 + yy - 1, gx = x0 + xx - 1;
            float v = 0.f;
            if (gy >= 0 && gy < HH && gx >= 0 && gx < WW)
                v = xb[ic*HH*WW + gy*WW + gx];
            xs[yy][xx] = v;
        }
        for (int i = tid; i < 576; i += 256) {
            int oc = i / 9, k = i % 9;
            ws[oc][k] = w[oc*576 + ic*9 + k];
        }
        __syncthreads();
        float xv[9];
#pragma unroll
        for (int dy = 0; dy < 3; dy++)
#pragma unroll
            for (int dx = 0; dx < 3; dx++)
                xv[dy*3+dx] = xs[py+dy][px+dx];
        float lap = xv[1] + xv[3] + xv[5] + xv[7] - 4.f*xv[4];
#pragma unroll
        for (int oc = 0; oc < 64; oc++) {
            float a = acc[oc];
#pragma unroll
            for (int k = 0; k < 9; k++) a = fmaf(xv[k], ws[oc][k], a);
            acc[oc] = a + ((oc == ic) ? lap : 0.f);
        }
        __syncthreads();
    }
    float* fb = g_feat + b*CC*HH*WW + (y0+py)*WW + x0 + px;
#pragma unroll
    for (int oc = 0; oc < 64; oc++)
        fb[oc*HH*WW] = acc[oc];
}

// ---------------- Stage 2a: pool + transpose to [B][N][C] ----------------
template<int S>
__global__ void __launch_bounds__(256) pool_kernel() {
    constexpr int WP = WW / S;
    constexpr int N  = (HH/S) * (WW/S);
    float* out = (S == 1) ? g_f1 : (S == 2) ? g_f2 : g_f4;
    __shared__ float tile[32][33];
    const int b  = blockIdx.z;
    const int c0 = blockIdx.y * 32;
    const int n0 = blockIdx.x * 32;
    const int tid = threadIdx.x;
    const int tx = tid & 31, ty = tid >> 5;
    for (int ci = ty; ci < 32; ci += 8) {
        int n = n0 + tx;
        int ny = n / WP, nx = n % WP;
        const float* fp = g_feat + ((b*CC + c0 + ci)*HH + ny*S)*WW + nx*S;
        float s = 0.f;
#pragma unroll
        for (int dy = 0; dy < S; dy++)
#pragma unroll
            for (int dx = 0; dx < S; dx++)
                s += fp[dy*WW + dx];
        tile[ci][tx] = s * (1.f/(S*S));
    }
    __syncthreads();
    for (int ni = ty; ni < 32; ni += 8)
        out[(b*N + n0 + ni)*CC + c0 + tx] = tile[tx][ni];
}

// ---------------- Stage 2b: mma.sync flash attention (tf32 main + bf16 corrections) ----------------
// CTA: 128 queries, 256 threads (8 warps), 64-key tiles. Warp w owns q-rows [16w,16w+16).
// f32 tiles stride 72 words, k-interleaved pairs (j, j+4) -> all fragment reads are LDS.64,
// conflict-free. bf16 tiles: packed words, stride 40, same interleave in word space.
#define TSTR 72
#define BSTR 40
#define ATTN_SMEM ((128*TSTR*2 + 64*TSTR*2 + 128*BSTR*2 + 64*BSTR*2) * 4)

template<int N>
__global__ void __launch_bounds__(256, 1) attn_mma() {
    const float* f = (N == 4096) ? g_f1 : (N == 1024) ? g_f2 : g_f4;
    float* outp    = (N == 4096) ? g_o1 : (N == 1024) ? g_o2 : g_o4;
    extern __shared__ float sm[];
    float* QH = sm;                         // [128][72] tf32 hi
    float* PT = QH + 128*TSTR;              // [128][72] tf32 P
    float* KH = PT + 128*TSTR;              // [64][72]  tf32 hi
    float* VT = KH + 64*TSTR;               // [64ch][72keys] tf32 V^T
    uint32_t* Qhb = (uint32_t*)(VT + 64*TSTR);  // [128][40] bf16x2
    uint32_t* Qlb = Qhb + 128*BSTR;
    uint32_t* Khb = Qlb + 128*BSTR;
    uint32_t* Klb = Khb + 64*BSTR;

    const int tid  = threadIdx.x;
    const int w    = tid >> 5;
    const int lane = tid & 31;
    const int g    = lane >> 2;
    const int q4   = lane & 3;
    const int b    = blockIdx.y;
    const int q0   = blockIdx.x * 128;
    const float* fb = f + (size_t)b * N * 64;
    const int r0 = w*16 + g;

    // ---- stage Q: tf32 hi (f32) + bf16 hi/lo ----
    {
        int row = tid >> 1, half = tid & 1;
        const float4* src = (const float4*)(fb + (size_t)(q0 + row)*64 + half*32);
        float* qh = QH + row*TSTR;
        uint32_t* qhb = Qhb + row*BSTR;
        uint32_t* qlb = Qlb + row*BSTR;
#pragma unroll
        for (int i = 0; i < 8; i++) {
            float4 v = src[i];
            float hx = tf32r(v.x), hy = tf32r(v.y), hz = tf32r(v.z), hw = tf32r(v.w);
            float lx = v.x-hx, ly = v.y-hy, lz = v.z-hz, lw = v.w-hw;
            int c0 = half*32 + i*4;
            int base = (c0 >> 3)*8 + ((c0 & 7) >> 2);
            qh[base+0]=hx; qh[base+2]=hy; qh[base+4]=hz; qh[base+6]=hw;
            int w0 = c0 >> 1, u = w0 & 7, bw = (w0 >> 3)*8;
            qhb[bw + islot(u)]   = packbf(hx, hy);
            qhb[bw + islot(u+1)] = packbf(hz, hw);
            qlb[bw + islot(u)]   = packbf(lx, ly);
            qlb[bw + islot(u+1)] = packbf(lz, lw);
        }
    }

    float m0 = -3.0e38f, m1 = -3.0e38f, l0 = 0.f, l1 = 0.f;
    float o[8][4];
#pragma unroll
    for (int nb = 0; nb < 8; nb++)
#pragma unroll
        for (int j = 0; j < 4; j++) o[nb][j] = 0.f;

    const int sl0 = islot(2*q4), sl1 = islot(2*q4 + 1);

    for (int kb = 0; kb < N/64; kb++) {
        __syncthreads();   // prior-iteration reads done (also publishes Q on kb=0)
        // ---- stage K tile: tf32 hi + bf16 hi/lo + transposed V ----
        {
            int row = tid >> 2, part = tid & 3;
            const float4* src = (const float4*)(fb + (size_t)(kb*64 + row)*64 + part*16);
            float* kh = KH + row*TSTR;
            uint32_t* khb = Khb + row*BSTR;
            uint32_t* klb = Klb + row*BSTR;
            int vs = (row >> 3)*8 + islot(row & 7);
#pragma unroll
            for (int i = 0; i < 4; i++) {
                float4 v = src[i];
                float hx = tf32r(v.x), hy = tf32r(v.y), hz = tf32r(v.z), hw = tf32r(v.w);
                float lx = v.x-hx, ly = v.y-hy, lz = v.z-hz, lw = v.w-hw;
                int c0 = part*16 + i*4;
                int base = (c0 >> 3)*8 + ((c0 & 7) >> 2);
                kh[base+0]=hx; kh[base+2]=hy; kh[base+4]=hz; kh[base+6]=hw;
                VT[(c0+0)*TSTR + vs] = hx;
                VT[(c0+1)*TSTR + vs] = hy;
                VT[(c0+2)*TSTR + vs] = hz;
                VT[(c0+3)*TSTR + vs] = hw;
                int w0 = c0 >> 1, u = w0 & 7, bw = (w0 >> 3)*8;
                khb[bw + islot(u)]   = packbf(hx, hy);
                khb[bw + islot(u+1)] = packbf(hz, hw);
                klb[bw + islot(u)]   = packbf(lx, ly);
                klb[bw + islot(u+1)] = packbf(lz, lw);
            }
        }
        __syncthreads();

        // ---- S = Qh*Kh (tf32) + [Qh*Kl + Ql*Kh] (bf16) ----
        float s[8][4];
#pragma unroll
        for (int nb = 0; nb < 8; nb++)
#pragma unroll
            for (int j = 0; j < 4; j++) s[nb][j] = 0.f;

#pragma unroll
        for (int ks = 0; ks < 8; ks++) {
            uint2 aA = *(const uint2*)(QH +  r0    *TSTR + ks*8 + 2*q4);
            uint2 aB = *(const uint2*)(QH + (r0+8) *TSTR + ks*8 + 2*q4);
#pragma unroll
            for (int nb = 0; nb < 8; nb++) {
                uint2 bb = *(const uint2*)(KH + (nb*8+g)*TSTR + ks*8 + 2*q4);
                mma8(s[nb], aA.x, aB.x, aA.y, aB.y, bb.x, bb.y);
            }
        }
#pragma unroll
        for (int pass = 0; pass < 2; pass++) {
            const uint32_t* Ab = pass ? Qlb : Qhb;
            const uint32_t* Bb = pass ? Khb : Klb;
#pragma unroll
            for (int ks = 0; ks < 4; ks++) {
                uint2 aA = *(const uint2*)(Ab +  r0    *BSTR + ks*8 + 2*q4);
                uint2 aB = *(const uint2*)(Ab + (r0+8) *BSTR + ks*8 + 2*q4);
#pragma unroll
                for (int nb = 0; nb < 8; nb++) {
                    uint2 bb = *(const uint2*)(Bb + (nb*8+g)*BSTR + ks*8 + 2*q4);
                    mma16(s[nb], aA.x, aB.x, aA.y, aB.y, bb.x, bb.y);
                }
            }
        }

        // ---- online softmax (rows r0 / r0+8; quad reductions) ----
        float mx0 = -3.0e38f, mx1 = -3.0e38f;
#pragma unroll
        for (int nb = 0; nb < 8; nb++) {
            mx0 = fmaxf(mx0, fmaxf(s[nb][0], s[nb][1]));
            mx1 = fmaxf(mx1, fmaxf(s[nb][2], s[nb][3]));
        }
        mx0 = fmaxf(mx0, __shfl_xor_sync(0xffffffffu, mx0, 1));
        mx0 = fmaxf(mx0, __shfl_xor_sync(0xffffffffu, mx0, 2));
        mx1 = fmaxf(mx1, __shfl_xor_sync(0xffffffffu, mx1, 1));
        mx1 = fmaxf(mx1, __shfl_xor_sync(0xffffffffu, mx1, 2));
        float mn0 = fmaxf(m0, mx0), mn1 = fmaxf(m1, mx1);
        float c0f = __expf(m0 - mn0), c1f = __expf(m1 - mn1);
        m0 = mn0; m1 = mn1;
        float sum0 = 0.f, sum1 = 0.f;
#pragma unroll
        for (int nb = 0; nb < 8; nb++) {
            s[nb][0] = __expf(s[nb][0] - mn0); sum0 += s[nb][0];
            s[nb][1] = __expf(s[nb][1] - mn0); sum0 += s[nb][1];
            s[nb][2] = __expf(s[nb][2] - mn1); sum1 += s[nb][2];
            s[nb][3] = __expf(s[nb][3] - mn1); sum1 += s[nb][3];
        }
        sum0 += __shfl_xor_sync(0xffffffffu, sum0, 1);
        sum0 += __shfl_xor_sync(0xffffffffu, sum0, 2);
        sum1 += __shfl_xor_sync(0xffffffffu, sum1, 1);
        sum1 += __shfl_xor_sync(0xffffffffu, sum1, 2);
        l0 = l0*c0f + sum0;
        l1 = l1*c1f + sum1;
#pragma unroll
        for (int nb = 0; nb < 8; nb++) {
            o[nb][0] *= c0f; o[nb][1] *= c0f;
            o[nb][2] *= c1f; o[nb][3] *= c1f;
        }

        // ---- stage P (tf32, interleaved) — warp-private rows ----
#pragma unroll
        for (int nb = 0; nb < 8; nb++) {
            PT[ r0    *TSTR + nb*8 + sl0] = tf32r(s[nb][0]);
            PT[ r0    *TSTR + nb*8 + sl1] = tf32r(s[nb][1]);
            PT[(r0+8) *TSTR + nb*8 + sl0] = tf32r(s[nb][2]);
            PT[(r0+8) *TSTR + nb*8 + sl1] = tf32r(s[nb][3]);
        }
        __syncwarp();

        // ---- O += P @ V ----
#pragma unroll
        for (int ks = 0; ks < 8; ks++) {
            uint2 aA = *(const uint2*)(PT +  r0    *TSTR + ks*8 + 2*q4);
            uint2 aB = *(const uint2*)(PT + (r0+8) *TSTR + ks*8 + 2*q4);
#pragma unroll
            for (int nb = 0; nb < 8; nb++) {
                uint2 bb = *(const uint2*)(VT + (nb*8+g)*TSTR + ks*8 + 2*q4);
                mma8(o[nb], aA.x, aB.x, aA.y, aB.y, bb.x, bb.y);
            }
        }
    }

    // ---- epilogue: normalize, write [B][C][N] ----
    float i0 = 1.f / l0, i1 = 1.f / l1;
    float* ob = outp + (size_t)b * 64 * N;
#pragma unroll
    for (int nb = 0; nb < 8; nb++) {
        int c = nb*8 + 2*q4;
        ob[(size_t) c   *N + q0 + r0    ] = o[nb][0]*i0;
        ob[(size_t)(c+1)*N + q0 + r0    ] = o[nb][1]*i0;
        ob[(size_t) c   *N + q0 + r0 + 8] = o[nb][2]*i1;
        ob[(size_t)(c+1)*N + q0 + r0 + 8] = o[nb][3]*i1;
    }
}

// ---------------- Stage 3: bilinear upsample + residual ----------------
__device__ __forceinline__ float bilin(const float* __restrict__ p, int hp,
                                       int y, int x, float inv_s) {
    float sy = (y + 0.5f)*inv_s - 0.5f;
    float sx = (x + 0.5f)*inv_s - 0.5f;
    float fy = floorf(sy), fx = floorf(sx);
    float wy = sy - fy, wx = sx - fx;
    int y0 = max((int)fy, 0), y1 = min((int)fy + 1, hp-1);
    int x0 = max((int)fx, 0), x1 = min((int)fx + 1, hp-1);
    float a = p[y0*hp + x0], b2 = p[y0*hp + x1];
    float c2 = p[y1*hp + x0], d2 = p[y1*hp + x1];
    return (a*(1.f-wx) + b2*wx)*(1.f-wy) + (c2*(1.f-wx) + d2*wx)*wy;
}

__global__ void __launch_bounds__(256) final_kernel(const float* __restrict__ x,
                                                    float* __restrict__ out) {
    int idx = blockIdx.x*256 + threadIdx.x;
    if (idx >= BB*CC*HH*WW) return;
    int xx = idx & 63, yy = (idx >> 6) & 63, bc = idx >> 12;
    float v = x[idx] + g_o1[idx];
    v += bilin(g_o2 + bc*1024, 32, yy, xx, 0.5f);
    v += bilin(g_o4 + bc*256,  16, yy, xx, 0.25f);
    out[idx] = v;
}

// ---------------- launch ----------------
extern "C" void kernel_launch(void* const* d_in, const int* in_sizes, int n_in,
                              void* d_out, int out_size) {
    const float* x = (const float*)d_in[0];
    const float* w = (const float*)d_in[1];
    float* out = (float*)d_out;

    cudaFuncSetAttribute(attn_mma<4096>, cudaFuncAttributeMaxDynamicSharedMemorySize, ATTN_SMEM);
    cudaFuncSetAttribute(attn_mma<1024>, cudaFuncAttributeMaxDynamicSharedMemorySize, ATTN_SMEM);
    cudaFuncSetAttribute(attn_mma<256>,  cudaFuncAttributeMaxDynamicSharedMemorySize, ATTN_SMEM);

    conv_kernel<<<dim3(16, 8), 256>>>(x, w);
    pool_kernel<1><<<dim3(128, 2, 8), 256>>>();
    pool_kernel<2><<<dim3(32, 2, 8), 256>>>();
    pool_kernel<4><<<dim3(8, 2, 8), 256>>>();
    attn_mma<4096><<<dim3(32, 8), 256, ATTN_SMEM>>>();
    attn_mma<1024><<<dim3(8, 8),  256, ATTN_SMEM>>>();
    attn_mma<256> <<<dim3(2, 8),  256, ATTN_SMEM>>>();
    final_kernel<<<(BB*CC*HH*WW + 255)/256, 256>>>(x, out);
}

// round 5
// speedup vs baseline: 1.2241x; 1.2241x over previous
#include <cuda_runtime.h>
#include <cuda_fp16.h>
#include <cstdint>
#include <math.h>

#define BB 8
#define CC 64
#define HH 64
#define WW 64

// ---------------- scratch (static device globals; no allocation) ----------------
__device__ float g_feat[BB*CC*HH*WW];      // [B][C][H][W]
__device__ float g_f1[BB*4096*CC];         // [B][N][C] pooled/transposed features
__device__ float g_f2[BB*1024*CC];
__device__ float g_f4[BB*256*CC];
__device__ float g_o1[BB*CC*4096];         // [B][C][n] attention outputs
__device__ float g_o2[BB*CC*1024];
__device__ float g_o4[BB*CC*256];

__device__ __forceinline__ uint32_t packh(float lo, float hi) {  // word = {hi16, lo16}
    uint32_t r;
    asm("cvt.rn.f16x2.f32 %0, %1, %2;" : "=r"(r) : "f"(hi), "f"(lo));
    return r;
}
__device__ __forceinline__ int islot(int u) { return 2*(u & 3) + (u >> 2); }

// m16n8k16 fp16 MMA, row.col, f32 accumulate-in-place
__device__ __forceinline__ void mma16(float* d, uint32_t a0, uint32_t a1, uint32_t a2,
                                      uint32_t a3, uint32_t b0, uint32_t b1) {
    asm volatile("mma.sync.aligned.m16n8k16.row.col.f32.f16.f16.f32 "
        "{%0,%1,%2,%3}, {%4,%5,%6,%7}, {%8,%9}, {%0,%1,%2,%3};"
        : "+f"(d[0]), "+f"(d[1]), "+f"(d[2]), "+f"(d[3])
        : "r"(a0), "r"(a1), "r"(a2), "r"(a3), "r"(b0), "r"(b1));
}

// ---------------- Stage 1: 3x3 conv + depthwise Laplacian ----------------
__global__ void __launch_bounds__(256) conv_kernel(const float* __restrict__ x,
                                                   const float* __restrict__ w) {
    __shared__ float xs[18][18];
    __shared__ float ws[64][9];
    const int tile = blockIdx.x;
    const int b = blockIdx.y;
    const int y0 = (tile >> 2) << 4;
    const int x0 = (tile & 3) << 4;
    const int tid = threadIdx.x;
    const int px = tid & 15, py = tid >> 4;
    float acc[64];
#pragma unroll
    for (int i = 0; i < 64; i++) acc[i] = 0.f;
    const float* xb = x + b*CC*HH*WW;
    for (int ic = 0; ic < 64; ic++) {
        for (int i = tid; i < 18*18; i += 256) {
            int yy = i / 18, xx = i % 18;
            int gy = y0 + yy - 1, gx = x0 + xx - 1;
            float v = 0.f;
            if (gy >= 0 && gy < HH && gx >= 0 && gx < WW)
                v = xb[ic*HH*WW + gy*WW + gx];
            xs[yy][xx] = v;
        }
        for (int i = tid; i < 576; i += 256) {
            int oc = i / 9, k = i % 9;
            ws[oc][k] = w[oc*576 + ic*9 + k];
        }
        __syncthreads();
        float xv[9];
#pragma unroll
        for (int dy = 0; dy < 3; dy++)
#pragma unroll
            for (int dx = 0; dx < 3; dx++)
                xv[dy*3+dx] = xs[py+dy][px+dx];
        float lap = xv[1] + xv[3] + xv[5] + xv[7] - 4.f*xv[4];
#pragma unroll
        for (int oc = 0; oc < 64; oc++) {
            float a = acc[oc];
#pragma unroll
            for (int k = 0; k < 9; k++) a = fmaf(xv[k], ws[oc][k], a);
            acc[oc] = a + ((oc == ic) ? lap : 0.f);
        }
        __syncthreads();
    }
    float* fb = g_feat + b*CC*HH*WW + (y0+py)*WW + x0 + px;
#pragma unroll
    for (int oc = 0; oc < 64; oc++)
        fb[oc*HH*WW] = acc[oc];
}

// ---------------- Stage 2a: pool + transpose to [B][N][C] ----------------
template<int S>
__global__ void __launch_bounds__(256) pool_kernel() {
    constexpr int WP = WW / S;
    constexpr int N  = (HH/S) * (WW/S);
    float* out = (S == 1) ? g_f1 : (S == 2) ? g_f2 : g_f4;
    __shared__ float tile[32][33];
    const int b  = blockIdx.z;
    const int c0 = blockIdx.y * 32;
    const int n0 = blockIdx.x * 32;
    const int tid = threadIdx.x;
    const int tx = tid & 31, ty = tid >> 5;
    for (int ci = ty; ci < 32; ci += 8) {
        int n = n0 + tx;
        int ny = n / WP, nx = n % WP;
        const float* fp = g_feat + ((b*CC + c0 + ci)*HH + ny*S)*WW + nx*S;
        float s = 0.f;
#pragma unroll
        for (int dy = 0; dy < S; dy++)
#pragma unroll
            for (int dx = 0; dx < S; dx++)
                s += fp[dy*WW + dx];
        tile[ci][tx] = s * (1.f/(S*S));
    }
    __syncthreads();
    for (int ni = ty; ni < 32; ni += 8)
        out[(b*N + n0 + ni)*CC + c0 + tx] = tile[tx][ni];
}

// ---------------- Stage 2b: fp16-split mma.sync flash attention ----------------
// CTA: 64 queries, 128 threads (4 warps), 64-key tiles, 3 CTAs/SM.
// All tiles fp16x2 words, row stride 40 words, interleaved pairs (j, j+4) so every
// fragment read is one conflict-free LDS.64.
// S = Qh*Kh (exact in f32) + (Qh*Kl' + Ql'*Kh)/2048, lo' = (v - hi)*2048.
#define BSTR 40
#define TS   (64*BSTR)
#define ATTN_SMEM (6*TS*4)

template<int N>
__global__ void __launch_bounds__(128, 3) attn_mma() {
    const float* f = (N == 4096) ? g_f1 : (N == 1024) ? g_f2 : g_f4;
    float* outp    = (N == 4096) ? g_o1 : (N == 1024) ? g_o2 : g_o4;
    extern __shared__ uint32_t smw[];
    uint32_t* Qh = smw;
    uint32_t* Ql = smw + TS;
    uint32_t* Pt = smw + 2*TS;
    uint32_t* Kh = smw + 3*TS;
    uint32_t* Kl = smw + 4*TS;
    uint32_t* Vt = smw + 5*TS;

    const int tid  = threadIdx.x;
    const int w    = tid >> 5;
    const int lane = tid & 31;
    const int g    = lane >> 2;
    const int q4   = lane & 3;
    const int b    = blockIdx.y;
    const int q0   = blockIdx.x * 64;
    const float* fb = f + (size_t)b * N * 64;
    const int r0 = w*16 + g;

    // ---- stage Q (split hi / scaled-lo) ----
    {
        int row = tid >> 1, half = tid & 1;
        const float4* src = (const float4*)(fb + (size_t)(q0 + row)*64 + half*32);
        uint32_t* qh = Qh + row*BSTR;
        uint32_t* ql = Ql + row*BSTR;
#pragma unroll
        for (int i = 0; i < 8; i++) {
            float4 v = src[i];
            uint32_t h0 = packh(v.x, v.y), h1 = packh(v.z, v.w);
            float2 f0 = __half22float2(*(const __half2*)&h0);
            float2 f1 = __half22float2(*(const __half2*)&h1);
            uint32_t l0 = packh((v.x - f0.x)*2048.f, (v.y - f0.y)*2048.f);
            uint32_t l1 = packh((v.z - f1.x)*2048.f, (v.w - f1.y)*2048.f);
            int lw = half*16 + i*2;                 // even logical word
            int base = (lw >> 3)*8, u = lw & 7;
            qh[base + islot(u)]   = h0;
            qh[base + islot(u+1)] = h1;
            ql[base + islot(u)]   = l0;
            ql[base + islot(u+1)] = l1;
        }
    }

    float m0 = -3.0e38f, m1 = -3.0e38f, l0s = 0.f, l1s = 0.f;
    float o[8][4];
#pragma unroll
    for (int nb = 0; nb < 8; nb++)
#pragma unroll
        for (int j = 0; j < 4; j++) o[nb][j] = 0.f;

    for (int kb = 0; kb < N/64; kb++) {
        __syncthreads();   // previous-iteration reads done (also publishes Q on kb=0)
        // ---- stage K tile (split) + fp16 V transposed ----
        {
            int key = tid >> 1, half = tid & 1;
            const float4* src = (const float4*)(fb + (size_t)(kb*64 + key)*64 + half*32);
            uint32_t* kh = Kh + key*BSTR;
            uint32_t* kl = Kl + key*BSTR;
            int lwv = key >> 1;
            int slotv = (lwv >> 3)*8 + islot(lwv & 7);
            char* vtb = (char*)Vt + slotv*4 + (key & 1)*2;
#pragma unroll
            for (int i = 0; i < 8; i++) {
                float4 v = src[i];
                uint32_t h0 = packh(v.x, v.y), h1 = packh(v.z, v.w);
                float2 f0 = __half22float2(*(const __half2*)&h0);
                float2 f1 = __half22float2(*(const __half2*)&h1);
                uint32_t l0 = packh((v.x - f0.x)*2048.f, (v.y - f0.y)*2048.f);
                uint32_t l1 = packh((v.z - f1.x)*2048.f, (v.w - f1.y)*2048.f);
                int lw = half*16 + i*2;
                int base = (lw >> 3)*8, u = lw & 7;
                kh[base + islot(u)]   = h0;
                kh[base + islot(u+1)] = h1;
                kl[base + islot(u)]   = l0;
                kl[base + islot(u+1)] = l1;
                int c0 = half*32 + i*4;
                __half2 hh0 = *(const __half2*)&h0;
                __half2 hh1 = *(const __half2*)&h1;
                *(__half*)(vtb + (c0+0)*BSTR*4) = __low2half(hh0);
                *(__half*)(vtb + (c0+1)*BSTR*4) = __high2half(hh0);
                *(__half*)(vtb + (c0+2)*BSTR*4) = __low2half(hh1);
                *(__half*)(vtb + (c0+3)*BSTR*4) = __high2half(hh1);
            }
        }
        __syncthreads();

        // ---- S: corrections first (scaled x2048), then scale, then exact hh ----
        float s[8][4];
#pragma unroll
        for (int nb = 0; nb < 8; nb++)
#pragma unroll
            for (int j = 0; j < 4; j++) s[nb][j] = 0.f;

#pragma unroll
        for (int pass = 0; pass < 2; pass++) {
            const uint32_t* Ab = pass ? Ql : Qh;
            const uint32_t* Bb = pass ? Kh : Kl;
#pragma unroll
            for (int ks = 0; ks < 4; ks++) {
                uint2 aA = *(const uint2*)(Ab +  r0    *BSTR + ks*8 + 2*q4);
                uint2 aB = *(const uint2*)(Ab + (r0+8) *BSTR + ks*8 + 2*q4);
#pragma unroll
                for (int nb = 0; nb < 8; nb++) {
                    uint2 bb = *(const uint2*)(Bb + (nb*8+g)*BSTR + ks*8 + 2*q4);
                    mma16(s[nb], aA.x, aB.x, aA.y, aB.y, bb.x, bb.y);
                }
            }
        }
#pragma unroll
        for (int nb = 0; nb < 8; nb++)
#pragma unroll
            for (int j = 0; j < 4; j++) s[nb][j] *= 4.8828125e-4f;   // /2048
#pragma unroll
        for (int ks = 0; ks < 4; ks++) {
            uint2 aA = *(const uint2*)(Qh +  r0    *BSTR + ks*8 + 2*q4);
            uint2 aB = *(const uint2*)(Qh + (r0+8) *BSTR + ks*8 + 2*q4);
#pragma unroll
            for (int nb = 0; nb < 8; nb++) {
                uint2 bb = *(const uint2*)(Kh + (nb*8+g)*BSTR + ks*8 + 2*q4);
                mma16(s[nb], aA.x, aB.x, aA.y, aB.y, bb.x, bb.y);
            }
        }

        // ---- online softmax (rows r0 / r0+8; quad reductions) ----
        float mx0 = -3.0e38f, mx1 = -3.0e38f;
#pragma unroll
        for (int nb = 0; nb < 8; nb++) {
            mx0 = fmaxf(mx0, fmaxf(s[nb][0], s[nb][1]));
            mx1 = fmaxf(mx1, fmaxf(s[nb][2], s[nb][3]));
        }
        mx0 = fmaxf(mx0, __shfl_xor_sync(0xffffffffu, mx0, 1));
        mx0 = fmaxf(mx0, __shfl_xor_sync(0xffffffffu, mx0, 2));
        mx1 = fmaxf(mx1, __shfl_xor_sync(0xffffffffu, mx1, 1));
        mx1 = fmaxf(mx1, __shfl_xor_sync(0xffffffffu, mx1, 2));
        float mn0 = fmaxf(m0, mx0), mn1 = fmaxf(m1, mx1);
        float c0f = __expf(m0 - mn0), c1f = __expf(m1 - mn1);
        m0 = mn0; m1 = mn1;
        float sum0 = 0.f, sum1 = 0.f;
#pragma unroll
        for (int nb = 0; nb < 8; nb++) {
            s[nb][0] = __expf(s[nb][0] - mn0); sum0 += s[nb][0];
            s[nb][1] = __expf(s[nb][1] - mn0); sum0 += s[nb][1];
            s[nb][2] = __expf(s[nb][2] - mn1); sum1 += s[nb][2];
            s[nb][3] = __expf(s[nb][3] - mn1); sum1 += s[nb][3];
        }
        sum0 += __shfl_xor_sync(0xffffffffu, sum0, 1);
        sum0 += __shfl_xor_sync(0xffffffffu, sum0, 2);
        sum1 += __shfl_xor_sync(0xffffffffu, sum1, 1);
        sum1 += __shfl_xor_sync(0xffffffffu, sum1, 2);
        l0s = l0s*c0f + sum0;
        l1s = l1s*c1f + sum1;
#pragma unroll
        for (int nb = 0; nb < 8; nb++) {
            o[nb][0] *= c0f; o[nb][1] *= c0f;
            o[nb][2] *= c1f; o[nb][3] *= c1f;
        }

        // ---- stage P (fp16, warp-private rows) ----
#pragma unroll
        for (int nb = 0; nb < 8; nb++) {
            int lw = nb*4 + q4;
            int slot = (lw >> 3)*8 + islot(lw & 7);
            Pt[ r0    *BSTR + slot] = packh(s[nb][0], s[nb][1]);
            Pt[(r0+8) *BSTR + slot] = packh(s[nb][2], s[nb][3]);
        }
        __syncwarp();

        // ---- O += P @ V ----
#pragma unroll
        for (int ks = 0; ks < 4; ks++) {
            uint2 aA = *(const uint2*)(Pt +  r0    *BSTR + ks*8 + 2*q4);
            uint2 aB = *(const uint2*)(Pt + (r0+8) *BSTR + ks*8 + 2*q4);
#pragma unroll
            for (int nb = 0; nb < 8; nb++) {
                uint2 bb = *(const uint2*)(Vt + (nb*8+g)*BSTR + ks*8 + 2*q4);
                mma16(o[nb], aA.x, aB.x, aA.y, aB.y, bb.x, bb.y);
            }
        }
    }

    // ---- epilogue: normalize, write [B][C][N] ----
    float i0 = 1.f / l0s, i1 = 1.f / l1s;
    float* ob = outp + (size_t)b * 64 * N;
#pragma unroll
    for (int nb = 0; nb < 8; nb++) {
        int c = nb*8 + 2*q4;
        ob[(size_t) c   *N + q0 + r0    ] = o[nb][0]*i0;
        ob[(size_t)(c+1)*N + q0 + r0    ] = o[nb][1]*i0;
        ob[(size_t) c   *N + q0 + r0 + 8] = o[nb][2]*i1;
        ob[(size_t)(c+1)*N + q0 + r0 + 8] = o[nb][3]*i1;
    }
}

// ---------------- Stage 3: bilinear upsample + residual ----------------
__device__ __forceinline__ float bilin(const float* __restrict__ p, int hp,
                                       int y, int x, float inv_s) {
    float sy = (y + 0.5f)*inv_s - 0.5f;
    float sx = (x + 0.5f)*inv_s - 0.5f;
    float fy = floorf(sy), fx = floorf(sx);
    float wy = sy - fy, wx = sx - fx;
    int y0 = max((int)fy, 0), y1 = min((int)fy + 1, hp-1);
    int x0 = max((int)fx, 0), x1 = min((int)fx + 1, hp-1);
    float a = p[y0*hp + x0], b2 = p[y0*hp + x1];
    float c2 = p[y1*hp + x0], d2 = p[y1*hp + x1];
    return (a*(1.f-wx) + b2*wx)*(1.f-wy) + (c2*(1.f-wx) + d2*wx)*wy;
}

__global__ void __launch_bounds__(256) final_kernel(const float* __restrict__ x,
                                                    float* __restrict__ out) {
    int idx = blockIdx.x*256 + threadIdx.x;
    if (idx >= BB*CC*HH*WW) return;
    int xx = idx & 63, yy = (idx >> 6) & 63, bc = idx >> 12;
    float v = x[idx] + g_o1[idx];
    v += bilin(g_o2 + bc*1024, 32, yy, xx, 0.5f);
    v += bilin(g_o4 + bc*256,  16, yy, xx, 0.25f);
    out[idx] = v;
}

// ---------------- launch ----------------
extern "C" void kernel_launch(void* const* d_in, const int* in_sizes, int n_in,
                              void* d_out, int out_size) {
    const float* x = (const float*)d_in[0];
    const float* w = (const float*)d_in[1];
    float* out = (float*)d_out;

    cudaFuncSetAttribute(attn_mma<4096>, cudaFuncAttributeMaxDynamicSharedMemorySize, ATTN_SMEM);
    cudaFuncSetAttribute(attn_mma<1024>, cudaFuncAttributeMaxDynamicSharedMemorySize, ATTN_SMEM);
    cudaFuncSetAttribute(attn_mma<256>,  cudaFuncAttributeMaxDynamicSharedMemorySize, ATTN_SMEM);

    conv_kernel<<<dim3(16, 8), 256>>>(x, w);
    pool_kernel<1><<<dim3(128, 2, 8), 256>>>();
    pool_kernel<2><<<dim3(32, 2, 8), 256>>>();
    pool_kernel<4><<<dim3(8, 2, 8), 256>>>();
    attn_mma<4096><<<dim3(64, 8), 128, ATTN_SMEM>>>();
    attn_mma<1024><<<dim3(16, 8), 128, ATTN_SMEM>>>();
    attn_mma<256> <<<dim3(4, 8),  128, ATTN_SMEM>>>();
    final_kernel<<<(BB*CC*HH*WW + 255)/256, 256>>>(x, out);
}

// round 6
// speedup vs baseline: 1.2407x; 1.0135x over previous
#include <cuda_runtime.h>
#include <cuda_fp16.h>
#include <cstdint>
#include <math.h>

#define BB 8
#define CC 64
#define HH 64
#define WW 64

// ---------------- scratch (static device globals; no allocation) ----------------
__device__ float g_feat[BB*CC*HH*WW];      // [B][C][H][W]
__device__ float g_wt[CC*9*CC];            // transposed weights [ic][k][oc]
__device__ float g_f1[BB*4096*CC];         // [B][N][C] pooled/transposed features
__device__ float g_f2[BB*1024*CC];
__device__ float g_f4[BB*256*CC];
__device__ float g_o1[BB*CC*4096];         // [B][C][n] attention outputs
__device__ float g_o2[BB*CC*1024];
__device__ float g_o4[BB*CC*256];

__device__ __forceinline__ uint32_t packh(float lo, float hi) {  // word = {hi16, lo16}
    uint32_t r;
    asm("cvt.rn.f16x2.f32 %0, %1, %2;" : "=r"(r) : "f"(hi), "f"(lo));
    return r;
}
__device__ __forceinline__ int islot(int u) { return 2*(u & 3) + (u >> 2); }

// m16n8k16 fp16 MMA, row.col, f32 accumulate-in-place
__device__ __forceinline__ void mma16(float* d, uint32_t a0, uint32_t a1, uint32_t a2,
                                      uint32_t a3, uint32_t b0, uint32_t b1) {
    asm volatile("mma.sync.aligned.m16n8k16.row.col.f32.f16.f16.f32 "
        "{%0,%1,%2,%3}, {%4,%5,%6,%7}, {%8,%9}, {%0,%1,%2,%3};"
        : "+f"(d[0]), "+f"(d[1]), "+f"(d[2]), "+f"(d[3])
        : "r"(a0), "r"(a1), "r"(a2), "r"(a3), "r"(b0), "r"(b1));
}

// ---------------- Stage 0: weight transpose  w[oc][ic][k] -> g_wt[ic][k][oc] ----------------
__global__ void __launch_bounds__(256) wtrans_kernel(const float* __restrict__ w) {
    int i = blockIdx.x*256 + threadIdx.x;     // i = ic*576 + k*64 + oc
    if (i >= CC*9*CC) return;
    int oc = i & 63, k = (i >> 6) % 9, ic = i / 576;
    g_wt[i] = w[oc*576 + ic*9 + k];
}

// ---------------- Stage 1: 3x3 conv + depthwise Laplacian ----------------
// 512 threads: 256 pixels (16x16 tile) x 2 oc-halves (32 oc each).
__global__ void __launch_bounds__(512) conv_kernel(const float* __restrict__ x) {
    __shared__ float xs[18][18];
    __shared__ float4 ws4[9*16];             // [k][oc/4] for current ic
    const int tile = blockIdx.x;
    const int b = blockIdx.y;
    const int y0 = (tile >> 2) << 4;
    const int x0 = (tile & 3) << 4;
    const int tid = threadIdx.x;
    const int px = tid & 255;
    const int half = tid >> 8;
    const int pxx = px & 15, py = px >> 4;
    float acc[32];
#pragma unroll
    for (int i = 0; i < 32; i++) acc[i] = 0.f;
    const float* xb = x + b*CC*HH*WW;
    for (int ic = 0; ic < 64; ic++) {
        if (tid < 18*18) {
            int yy = tid / 18, xx = tid % 18;
            int gy = y0 + yy - 1, gx = x0 + xx - 1;
            float v = 0.f;
            if (gy >= 0 && gy < HH && gx >= 0 && gx < WW)
                v = xb[ic*HH*WW + gy*WW + gx];
            xs[yy][xx] = v;
        }
        if (tid < 144)
            ws4[tid] = ((const float4*)(g_wt + ic*576))[tid];
        __syncthreads();
        float xv[9];
#pragma unroll
        for (int dy = 0; dy < 3; dy++)
#pragma unroll
            for (int dx = 0; dx < 3; dx++)
                xv[dy*3+dx] = xs[py+dy][pxx+dx];
#pragma unroll
        for (int k = 0; k < 9; k++) {
            float xk = xv[k];
#pragma unroll
            for (int g8 = 0; g8 < 8; g8++) {
                float4 wv = ws4[k*16 + half*8 + g8];
                acc[g8*4+0] = fmaf(xk, wv.x, acc[g8*4+0]);
                acc[g8*4+1] = fmaf(xk, wv.y, acc[g8*4+1]);
                acc[g8*4+2] = fmaf(xk, wv.z, acc[g8*4+2]);
                acc[g8*4+3] = fmaf(xk, wv.w, acc[g8*4+3]);
            }
        }
        if ((ic >> 5) == half) {   // Laplacian on channel ic
            float lap = xv[1] + xv[3] + xv[5] + xv[7] - 4.f*xv[4];
            acc[ic & 31] += lap;
        }
        __syncthreads();
    }
    float* fb = g_feat + b*CC*HH*WW + (y0+py)*WW + x0 + pxx;
#pragma unroll
    for (int j = 0; j < 32; j++)
        fb[(half*32 + j)*HH*WW] = acc[j];
}

// ---------------- Stage 2a: pool + transpose to [B][N][C] ----------------
template<int S>
__global__ void __launch_bounds__(256) pool_kernel() {
    constexpr int WP = WW / S;
    constexpr int N  = (HH/S) * (WW/S);
    float* out = (S == 1) ? g_f1 : (S == 2) ? g_f2 : g_f4;
    __shared__ float tile[32][33];
    const int b  = blockIdx.z;
    const int c0 = blockIdx.y * 32;
    const int n0 = blockIdx.x * 32;
    const int tid = threadIdx.x;
    const int tx = tid & 31, ty = tid >> 5;
    for (int ci = ty; ci < 32; ci += 8) {
        int n = n0 + tx;
        int ny = n / WP, nx = n % WP;
        const float* fp = g_feat + ((b*CC + c0 + ci)*HH + ny*S)*WW + nx*S;
        float s = 0.f;
#pragma unroll
        for (int dy = 0; dy < S; dy++)
#pragma unroll
            for (int dx = 0; dx < S; dx++)
                s += fp[dy*WW + dx];
        tile[ci][tx] = s * (1.f/(S*S));
    }
    __syncthreads();
    for (int ni = ty; ni < 32; ni += 8)
        out[(b*N + n0 + ni)*CC + c0 + tx] = tile[tx][ni];
}

// ---------------- Stage 2b: fp16-split mma.sync flash attention ----------------
// CTA: 64 queries, 128 threads (4 warps), 64-key tiles, 4 CTAs/SM (50KB smem).
// P never touches smem: the S C-fragment layout IS the PV A-fragment layout.
// S = Qh*Kh (f32 accum) + (Qh*Kl' + Ql'*Kh)/2048, lo' = (v-hi)*2048.
#define BSTR 40
#define TS   (64*BSTR)
#define ATTN_SMEM (5*TS*4)

template<int N>
__global__ void __launch_bounds__(128, 4) attn_mma() {
    const float* f = (N == 4096) ? g_f1 : (N == 1024) ? g_f2 : g_f4;
    float* outp    = (N == 4096) ? g_o1 : (N == 1024) ? g_o2 : g_o4;
    extern __shared__ uint32_t smw[];
    uint32_t* Qh = smw;
    uint32_t* Ql = smw + TS;
    uint32_t* Kh = smw + 2*TS;
    uint32_t* Kl = smw + 3*TS;
    uint32_t* Vt = smw + 4*TS;

    const int tid  = threadIdx.x;
    const int w    = tid >> 5;
    const int lane = tid & 31;
    const int g    = lane >> 2;
    const int q4   = lane & 3;
    const int b    = blockIdx.y;
    const int q0   = blockIdx.x * 64;
    const float* fb = f + (size_t)b * N * 64;
    const int r0 = w*16 + g;

    // ---- stage Q (split hi / scaled-lo) ----
    {
        int row = tid >> 1, half = tid & 1;
        const float4* src = (const float4*)(fb + (size_t)(q0 + row)*64 + half*32);
        uint32_t* qh = Qh + row*BSTR;
        uint32_t* ql = Ql + row*BSTR;
#pragma unroll
        for (int i = 0; i < 8; i++) {
            float4 v = src[i];
            uint32_t h0 = packh(v.x, v.y), h1 = packh(v.z, v.w);
            float2 f0 = __half22float2(*(const __half2*)&h0);
            float2 f1 = __half22float2(*(const __half2*)&h1);
            uint32_t l0 = packh((v.x - f0.x)*2048.f, (v.y - f0.y)*2048.f);
            uint32_t l1 = packh((v.z - f1.x)*2048.f, (v.w - f1.y)*2048.f);
            int lw = half*16 + i*2;
            int base = (lw >> 3)*8, u = lw & 7;
            qh[base + islot(u)]   = h0;
            qh[base + islot(u+1)] = h1;
            ql[base + islot(u)]   = l0;
            ql[base + islot(u+1)] = l1;
        }
    }

    float m0 = -3.0e38f, m1 = -3.0e38f, l0s = 0.f, l1s = 0.f;
    float o[8][4];
#pragma unroll
    for (int nb = 0; nb < 8; nb++)
#pragma unroll
        for (int j = 0; j < 4; j++) o[nb][j] = 0.f;

    for (int kb = 0; kb < N/64; kb++) {
        __syncthreads();   // previous-iteration reads done (also publishes Q on kb=0)
        // ---- stage K tile (split) + fp16 V transposed ----
        {
            int key = tid >> 1, half = tid & 1;
            const float4* src = (const float4*)(fb + (size_t)(kb*64 + key)*64 + half*32);
            uint32_t* kh = Kh + key*BSTR;
            uint32_t* kl = Kl + key*BSTR;
            int lwv = key >> 1;
            int slotv = (lwv >> 3)*8 + islot(lwv & 7);
            char* vtb = (char*)Vt + slotv*4 + (key & 1)*2;
#pragma unroll
            for (int i = 0; i < 8; i++) {
                float4 v = src[i];
                uint32_t h0 = packh(v.x, v.y), h1 = packh(v.z, v.w);
                float2 f0 = __half22float2(*(const __half2*)&h0);
                float2 f1 = __half22float2(*(const __half2*)&h1);
                uint32_t l0 = packh((v.x - f0.x)*2048.f, (v.y - f0.y)*2048.f);
                uint32_t l1 = packh((v.z - f1.x)*2048.f, (v.w - f1.y)*2048.f);
                int lw = half*16 + i*2;
                int base = (lw >> 3)*8, u = lw & 7;
                kh[base + islot(u)]   = h0;
                kh[base + islot(u+1)] = h1;
                kl[base + islot(u)]   = l0;
                kl[base + islot(u+1)] = l1;
                int c0 = half*32 + i*4;
                __half2 hh0 = *(const __half2*)&h0;
                __half2 hh1 = *(const __half2*)&h1;
                *(__half*)(vtb + (c0+0)*BSTR*4) = __low2half(hh0);
                *(__half*)(vtb + (c0+1)*BSTR*4) = __high2half(hh0);
                *(__half*)(vtb + (c0+2)*BSTR*4) = __low2half(hh1);
                *(__half*)(vtb + (c0+3)*BSTR*4) = __high2half(hh1);
            }
        }
        __syncthreads();

        // ---- S: correction passes first (scaled x2048), then /2048, then exact hh ----
        float s[8][4];
#pragma unroll
        for (int nb = 0; nb < 8; nb++)
#pragma unroll
            for (int j = 0; j < 4; j++) s[nb][j] = 0.f;

#pragma unroll
        for (int pass = 0; pass < 2; pass++) {
            const uint32_t* Ab = pass ? Ql : Qh;
            const uint32_t* Bb = pass ? Kh : Kl;
#pragma unroll
            for (int ks = 0; ks < 4; ks++) {
                uint2 aA = *(const uint2*)(Ab +  r0    *BSTR + ks*8 + 2*q4);
                uint2 aB = *(const uint2*)(Ab + (r0+8) *BSTR + ks*8 + 2*q4);
#pragma unroll
                for (int nb = 0; nb < 8; nb++) {
                    uint2 bb = *(const uint2*)(Bb + (nb*8+g)*BSTR + ks*8 + 2*q4);
                    mma16(s[nb], aA.x, aB.x, aA.y, aB.y, bb.x, bb.y);
                }
            }
        }
#pragma unroll
        for (int nb = 0; nb < 8; nb++)
#pragma unroll
            for (int j = 0; j < 4; j++) s[nb][j] *= 4.8828125e-4f;   // /2048
#pragma unroll
        for (int ks = 0; ks < 4; ks++) {
            uint2 aA = *(const uint2*)(Qh +  r0    *BSTR + ks*8 + 2*q4);
            uint2 aB = *(const uint2*)(Qh + (r0+8) *BSTR + ks*8 + 2*q4);
#pragma unroll
            for (int nb = 0; nb < 8; nb++) {
                uint2 bb = *(const uint2*)(Kh + (nb*8+g)*BSTR + ks*8 + 2*q4);
                mma16(s[nb], aA.x, aB.x, aA.y, aB.y, bb.x, bb.y);
            }
        }

        // ---- online softmax (rows r0 / r0+8; quad reductions) ----
        float mx0 = -3.0e38f, mx1 = -3.0e38f;
#pragma unroll
        for (int nb = 0; nb < 8; nb++) {
            mx0 = fmaxf(mx0, fmaxf(s[nb][0], s[nb][1]));
            mx1 = fmaxf(mx1, fmaxf(s[nb][2], s[nb][3]));
        }
        mx0 = fmaxf(mx0, __shfl_xor_sync(0xffffffffu, mx0, 1));
        mx0 = fmaxf(mx0, __shfl_xor_sync(0xffffffffu, mx0, 2));
        mx1 = fmaxf(mx1, __shfl_xor_sync(0xffffffffu, mx1, 1));
        mx1 = fmaxf(mx1, __shfl_xor_sync(0xffffffffu, mx1, 2));
        float mn0 = fmaxf(m0, mx0), mn1 = fmaxf(m1, mx1);
        float c0f = __expf(m0 - mn0), c1f = __expf(m1 - mn1);
        m0 = mn0; m1 = mn1;
        float sum0 = 0.f, sum1 = 0.f;
#pragma unroll
        for (int nb = 0; nb < 8; nb++) {
            s[nb][0] = __expf(s[nb][0] - mn0); sum0 += s[nb][0];
            s[nb][1] = __expf(s[nb][1] - mn0); sum0 += s[nb][1];
            s[nb][2] = __expf(s[nb][2] - mn1); sum1 += s[nb][2];
            s[nb][3] = __expf(s[nb][3] - mn1); sum1 += s[nb][3];
        }
        sum0 += __shfl_xor_sync(0xffffffffu, sum0, 1);
        sum0 += __shfl_xor_sync(0xffffffffu, sum0, 2);
        sum1 += __shfl_xor_sync(0xffffffffu, sum1, 1);
        sum1 += __shfl_xor_sync(0xffffffffu, sum1, 2);
        l0s = l0s*c0f + sum0;
        l1s = l1s*c1f + sum1;
#pragma unroll
        for (int nb = 0; nb < 8; nb++) {
            o[nb][0] *= c0f; o[nb][1] *= c0f;
            o[nb][2] *= c1f; o[nb][3] *= c1f;
        }

        // ---- O += P @ V directly from s fragments (no smem round-trip) ----
#pragma unroll
        for (int ks = 0; ks < 4; ks++) {
            uint32_t a0 = packh(s[2*ks  ][0], s[2*ks  ][1]);
            uint32_t a1 = packh(s[2*ks  ][2], s[2*ks  ][3]);
            uint32_t a2 = packh(s[2*ks+1][0], s[2*ks+1][1]);
            uint32_t a3 = packh(s[2*ks+1][2], s[2*ks+1][3]);
#pragma unroll
            for (int nb = 0; nb < 8; nb++) {
                uint2 bb = *(const uint2*)(Vt + (nb*8+g)*BSTR + ks*8 + 2*q4);
                mma16(o[nb], a0, a1, a2, a3, bb.x, bb.y);
            }
        }
    }

    // ---- epilogue: normalize, write [B][C][N] ----
    float i0 = 1.f / l0s, i1 = 1.f / l1s;
    float* ob = outp + (size_t)b * 64 * N;
#pragma unroll
    for (int nb = 0; nb < 8; nb++) {
        int c = nb*8 + 2*q4;
        ob[(size_t) c   *N + q0 + r0    ] = o[nb][0]*i0;
        ob[(size_t)(c+1)*N + q0 + r0    ] = o[nb][1]*i0;
        ob[(size_t) c   *N + q0 + r0 + 8] = o[nb][2]*i1;
        ob[(size_t)(c+1)*N + q0 + r0 + 8] = o[nb][3]*i1;
    }
}

// ---------------- Stage 3: bilinear upsample + residual ----------------
__device__ __forceinline__ float bilin(const float* __restrict__ p, int hp,
                                       int y, int x, float inv_s) {
    float sy = (y + 0.5f)*inv_s - 0.5f;
    float sx = (x + 0.5f)*inv_s - 0.5f;
    float fy = floorf(sy), fx = floorf(sx);
    float wy = sy - fy, wx = sx - fx;
    int y0 = max((int)fy, 0), y1 = min((int)fy + 1, hp-1);
    int x0 = max((int)fx, 0), x1 = min((int)fx + 1, hp-1);
    float a = p[y0*hp + x0], b2 = p[y0*hp + x1];
    float c2 = p[y1*hp + x0], d2 = p[y1*hp + x1];
    return (a*(1.f-wx) + b2*wx)*(1.f-wy) + (c2*(1.f-wx) + d2*wx)*wy;
}

__global__ void __launch_bounds__(256) final_kernel(const float* __restrict__ x,
                                                    float* __restrict__ out) {
    int idx = blockIdx.x*256 + threadIdx.x;
    if (idx >= BB*CC*HH*WW) return;
    int xx = idx & 63, yy = (idx >> 6) & 63, bc = idx >> 12;
    float v = x[idx] + g_o1[idx];
    v += bilin(g_o2 + bc*1024, 32, yy, xx, 0.5f);
    v += bilin(g_o4 + bc*256,  16, yy, xx, 0.25f);
    out[idx] = v;
}

// ---------------- launch ----------------
extern "C" void kernel_launch(void* const* d_in, const int* in_sizes, int n_in,
                              void* d_out, int out_size) {
    const float* x = (const float*)d_in[0];
    const float* w = (const float*)d_in[1];
    float* out = (float*)d_out;

    cudaFuncSetAttribute(attn_mma<4096>, cudaFuncAttributeMaxDynamicSharedMemorySize, ATTN_SMEM);
    cudaFuncSetAttribute(attn_mma<1024>, cudaFuncAttributeMaxDynamicSharedMemorySize, ATTN_SMEM);
    cudaFuncSetAttribute(attn_mma<256>,  cudaFuncAttributeMaxDynamicSharedMemorySize, ATTN_SMEM);

    wtrans_kernel<<<(CC*9*CC + 255)/256, 256>>>(w);
    conv_kernel<<<dim3(16, 8), 512>>>(x);
    pool_kernel<1><<<dim3(128, 2, 8), 256>>>();
    pool_kernel<2><<<dim3(32, 2, 8), 256>>>();
    pool_kernel<4><<<dim3(8, 2, 8), 256>>>();
    attn_mma<4096><<<dim3(64, 8), 128, ATTN_SMEM>>>();
    attn_mma<1024><<<dim3(16, 8), 128, ATTN_SMEM>>>();
    attn_mma<256> <<<dim3(4, 8),  128, ATTN_SMEM>>>();
    final_kernel<<<(BB*CC*HH*WW + 255)/256, 256>>>(x, out);
}

// round 7
// speedup vs baseline: 1.6164x; 1.3028x over previous
#include <cuda_runtime.h>
#include <cuda_fp16.h>
#include <cstdint>
#include <math.h>

#define BB 8
#define CC 64
#define HH 64
#define WW 64

#define BSTR 40              // words per row in fp16x2 tiles
#define SEGW 2560            // 64 rows * BSTR words  (10KB)
#define KWORDS (3*SEGW)      // packed tile: Kh | Kl | Vt (30KB)

// ---------------- scratch (static device globals; no allocation) ----------------
__device__ float g_feat[BB*CC*HH*WW];      // [B][C][H][W]
__device__ float g_wt[CC*9*CC];            // transposed weights [ic][k][oc]
__device__ float g_f1[BB*4096*CC];         // [B][N][C] pooled features (f32)
__device__ float g_f2[BB*1024*CC];
__device__ float g_f4[BB*256*CC];
__device__ uint32_t g_p1[BB*64*KWORDS];    // packed fp16 tiles per scale
__device__ uint32_t g_p2[BB*16*KWORDS];
__device__ uint32_t g_p4[BB*4*KWORDS];
__device__ float g_o1[BB*CC*4096];         // attention outputs [B][C][n]
__device__ float g_o2[BB*CC*1024];
__device__ float g_o4[BB*CC*256];

__device__ __forceinline__ uint32_t packh(float lo, float hi) {  // word = {hi16, lo16}
    uint32_t r;
    asm("cvt.rn.f16x2.f32 %0, %1, %2;" : "=r"(r) : "f"(hi), "f"(lo));
    return r;
}
__device__ __forceinline__ int islot(int u) { return 2*(u & 3) + (u >> 2); }
__device__ __forceinline__ uint32_t smem_u32(const void* p) {
    uint32_t a;
    asm("{ .reg .u64 t; cvta.to.shared.u64 t, %1; cvt.u32.u64 %0, t; }" : "=r"(a) : "l"(p));
    return a;
}
#define CP16(dst, src) asm volatile("cp.async.cg.shared.global [%0], [%1], 16;" :: "r"(dst), "l"(src))
#define CP_COMMIT()    asm volatile("cp.async.commit_group;" ::: "memory")
#define CP_WAIT1()     asm volatile("cp.async.wait_group 1;" ::: "memory")

// m16n8k16 fp16 MMA, row.col, f32 accumulate-in-place
__device__ __forceinline__ void mma16(float* d, uint32_t a0, uint32_t a1, uint32_t a2,
                                      uint32_t a3, uint32_t b0, uint32_t b1) {
    asm volatile("mma.sync.aligned.m16n8k16.row.col.f32.f16.f16.f32 "
        "{%0,%1,%2,%3}, {%4,%5,%6,%7}, {%8,%9}, {%0,%1,%2,%3};"
        : "+f"(d[0]), "+f"(d[1]), "+f"(d[2]), "+f"(d[3])
        : "r"(a0), "r"(a1), "r"(a2), "r"(a3), "r"(b0), "r"(b1));
}

// ---------------- Stage 0: weight transpose ----------------
__global__ void __launch_bounds__(256) wtrans_kernel(const float* __restrict__ w) {
    int i = blockIdx.x*256 + threadIdx.x;
    if (i >= CC*9*CC) return;
    int oc = i & 63, k = (i >> 6) % 9, ic = i / 576;
    g_wt[i] = w[oc*576 + ic*9 + k];
}

// ---------------- Stage 1: 3x3 conv + depthwise Laplacian ----------------
__global__ void __launch_bounds__(512) conv_kernel(const float* __restrict__ x) {
    __shared__ float xs[18][18];
    __shared__ float4 ws4[9*16];
    const int tile = blockIdx.x;
    const int b = blockIdx.y;
    const int y0 = (tile >> 2) << 4;
    const int x0 = (tile & 3) << 4;
    const int tid = threadIdx.x;
    const int px = tid & 255;
    const int half = tid >> 8;
    const int pxx = px & 15, py = px >> 4;
    float acc[32];
#pragma unroll
    for (int i = 0; i < 32; i++) acc[i] = 0.f;
    const float* xb = x + b*CC*HH*WW;
    for (int ic = 0; ic < 64; ic++) {
        if (tid < 18*18) {
            int yy = tid / 18, xx = tid % 18;
            int gy = y0 + yy - 1, gx = x0 + xx - 1;
            float v = 0.f;
            if (gy >= 0 && gy < HH && gx >= 0 && gx < WW)
                v = xb[ic*HH*WW + gy*WW + gx];
            xs[yy][xx] = v;
        }
        if (tid < 144)
            ws4[tid] = ((const float4*)(g_wt + ic*576))[tid];
        __syncthreads();
        float xv[9];
#pragma unroll
        for (int dy = 0; dy < 3; dy++)
#pragma unroll
            for (int dx = 0; dx < 3; dx++)
                xv[dy*3+dx] = xs[py+dy][pxx+dx];
#pragma unroll
        for (int k = 0; k < 9; k++) {
            float xk = xv[k];
#pragma unroll
            for (int g8 = 0; g8 < 8; g8++) {
                float4 wv = ws4[k*16 + half*8 + g8];
                acc[g8*4+0] = fmaf(xk, wv.x, acc[g8*4+0]);
                acc[g8*4+1] = fmaf(xk, wv.y, acc[g8*4+1]);
                acc[g8*4+2] = fmaf(xk, wv.z, acc[g8*4+2]);
                acc[g8*4+3] = fmaf(xk, wv.w, acc[g8*4+3]);
            }
        }
        if ((ic >> 5) == half) {
            float lap = xv[1] + xv[3] + xv[5] + xv[7] - 4.f*xv[4];
            acc[ic & 31] += lap;
        }
        __syncthreads();
    }
    float* fb = g_feat + b*CC*HH*WW + (y0+py)*WW + x0 + pxx;
#pragma unroll
    for (int j = 0; j < 32; j++)
        fb[(half*32 + j)*HH*WW] = acc[j];
}

// ---------------- Stage 2a: pool + transpose to [B][N][C] ----------------
template<int S>
__global__ void __launch_bounds__(256) pool_kernel() {
    constexpr int WP = WW / S;
    constexpr int N  = (HH/S) * (WW/S);
    float* out = (S == 1) ? g_f1 : (S == 2) ? g_f2 : g_f4;
    __shared__ float tile[32][33];
    const int b  = blockIdx.z;
    const int c0 = blockIdx.y * 32;
    const int n0 = blockIdx.x * 32;
    const int tid = threadIdx.x;
    const int tx = tid & 31, ty = tid >> 5;
    for (int ci = ty; ci < 32; ci += 8) {
        int n = n0 + tx;
        int ny = n / WP, nx = n % WP;
        const float* fp = g_feat + ((b*CC + c0 + ci)*HH + ny*S)*WW + nx*S;
        float s = 0.f;
#pragma unroll
        for (int dy = 0; dy < S; dy++)
#pragma unroll
            for (int dx = 0; dx < S; dx++)
                s += fp[dy*WW + dx];
        tile[ci][tx] = s * (1.f/(S*S));
    }
    __syncthreads();
    for (int ni = ty; ni < 32; ni += 8)
        out[(b*N + n0 + ni)*CC + c0 + tx] = tile[tx][ni];
}

// ---------------- Stage 2a': split/pack once per scale ----------------
// gpack[b][t]: [Kh(2560w) | Kl(2560w) | Vt(2560w)] fp16x2, smem-ready interleave.
template<int N>
__global__ void __launch_bounds__(256) split_kernel() {
    const float* f = (N == 4096) ? g_f1 : (N == 1024) ? g_f2 : g_f4;
    uint32_t* gpack = (N == 4096) ? g_p1 : (N == 1024) ? g_p2 : g_p4;
    const int t = blockIdx.x;
    const int b = blockIdx.y;
    const float* fb = f + ((size_t)b*N + t*64) * 64;
    uint32_t* gp = gpack + ((size_t)b*(N/64) + t) * KWORDS;
    const int tid = threadIdx.x;
    // segments 0/1: Kh/Kl  (row r, channel-pair word u)
#pragma unroll
    for (int j = 0; j < 8; j++) {
        int wi = j*256 + tid;           // 0..2047
        int r = wi >> 5, u = wi & 31;
        float a = fb[r*64 + 2*u];
        float c = fb[r*64 + 2*u + 1];
        uint32_t h = packh(a, c);
        float2 fh = __half22float2(*(const __half2*)&h);
        uint32_t l = packh((a - fh.x)*2048.f, (c - fh.y)*2048.f);
        int slot = r*BSTR + (u >> 3)*8 + islot(u & 7);
        gp[slot]        = h;
        gp[SEGW + slot] = l;
    }
    // segment 2: Vt (channel ch, key-pair word lwv)
#pragma unroll
    for (int j = 0; j < 8; j++) {
        int wi = j*256 + tid;
        int ch = wi >> 5, lwv = wi & 31;
        float a = fb[(2*lwv    )*64 + ch];
        float c = fb[(2*lwv + 1)*64 + ch];
        gp[2*SEGW + ch*BSTR + (lwv >> 3)*8 + islot(lwv & 7)] = packh(a, c);
    }
}

// ---------------- Stage 2b: fp16-split flash attention, cp.async pipeline ----------------
// CTA: 128 queries, 256 threads (8 warps), 64-key tiles, double-buffered K pack.
// smem words: Qh[5120] Ql[5120] KBUF0[7680] KBUF1[7680]  -> 100KB, 2 CTAs/SM.
#define Q_WORDS 5120
#define ATTN_SMEM ((2*Q_WORDS + 2*KWORDS) * 4)

template<int N>
__global__ void __launch_bounds__(256, 2) attn_mma() {
    float* outp = (N == 4096) ? g_o1 : (N == 1024) ? g_o2 : g_o4;
    const uint32_t* gpack = (N == 4096) ? g_p1 : (N == 1024) ? g_p2 : g_p4;
    extern __shared__ uint32_t smw[];
    uint32_t* Qh = smw;
    uint32_t* Ql = smw + Q_WORDS;
    uint32_t* KB[2] = { smw + 2*Q_WORDS, smw + 2*Q_WORDS + KWORDS };

    const int tid  = threadIdx.x;
    const int w    = tid >> 5;
    const int lane = tid & 31;
    const int g    = lane >> 2;
    const int q4   = lane & 3;
    const int b    = blockIdx.y;
    const int qt   = blockIdx.x;            // 128-query tile index
    const int r0   = w*16 + g;
    const int T    = N/64;
    const uint32_t* gb = gpack + (size_t)b*T*KWORDS;
    const uint32_t sb = smem_u32(smw);

    // group 0: Q (Kh/Kl of tiles 2qt, 2qt+1) + K tile 0
#pragma unroll
    for (int j = 0; j < 10; j++) {           // 2560 float4 total
        int i = j*256 + tid;
        int seg = i / 640;                   // 0:Qh p0  1:Qh p1  2:Ql p0  3:Ql p1
        int s = seg >> 1, p = seg & 1;
        int fo = (i - seg*640) * 4;          // word offset within segment
        const uint32_t* src = gb + (size_t)(2*qt + p)*KWORDS + s*SEGW + fo;
        CP16(sb + (s*Q_WORDS + p*SEGW + fo)*4, src);
    }
    {
        const uint32_t* src = gb;            // tile 0
#pragma unroll
        for (int j = 0; j < 8; j++) {
            int i = j*256 + tid;
            if (i < 1920) CP16(sb + (2*Q_WORDS + i*4)*4, src + i*4);
        }
    }
    CP_COMMIT();

    float m0 = -3.0e38f, m1 = -3.0e38f, l0s = 0.f, l1s = 0.f;
    float o[8][4];
#pragma unroll
    for (int nb = 0; nb < 8; nb++)
#pragma unroll
        for (int j = 0; j < 4; j++) o[nb][j] = 0.f;

    for (int kb = 0; kb < T; kb++) {
        // prefetch next tile (redundant copy of last tile on final iteration)
        {
            int nxt = (kb + 1 < T) ? kb + 1 : T - 1;
            const uint32_t* src = gb + (size_t)nxt*KWORDS;
            uint32_t dstb = sb + (2*Q_WORDS + ((kb + 1) & 1)*KWORDS)*4;
#pragma unroll
            for (int j = 0; j < 8; j++) {
                int i = j*256 + tid;
                if (i < 1920) CP16(dstb + i*16, src + i*4);
            }
            CP_COMMIT();
        }
        CP_WAIT1();
        __syncthreads();

        const uint32_t* Kh = KB[kb & 1];
        const uint32_t* Kl = Kh + SEGW;
        const uint32_t* Vt = Kh + 2*SEGW;

        // ---- S: corrections (scaled x2048) then /2048 then exact hh ----
        float s[8][4];
#pragma unroll
        for (int nb = 0; nb < 8; nb++)
#pragma unroll
            for (int j = 0; j < 4; j++) s[nb][j] = 0.f;

#pragma unroll
        for (int pass = 0; pass < 2; pass++) {
            const uint32_t* Ab = pass ? Ql : Qh;
            const uint32_t* Bb = pass ? Kh : Kl;
#pragma unroll
            for (int ks = 0; ks < 4; ks++) {
                uint2 aA = *(const uint2*)(Ab +  r0    *BSTR + ks*8 + 2*q4);
                uint2 aB = *(const uint2*)(Ab + (r0+8) *BSTR + ks*8 + 2*q4);
#pragma unroll
                for (int nb = 0; nb < 8; nb++) {
                    uint2 bb = *(const uint2*)(Bb + (nb*8+g)*BSTR + ks*8 + 2*q4);
                    mma16(s[nb], aA.x, aB.x, aA.y, aB.y, bb.x, bb.y);
                }
            }
        }
#pragma unroll
        for (int nb = 0; nb < 8; nb++)
#pragma unroll
            for (int j = 0; j < 4; j++) s[nb][j] *= 4.8828125e-4f;   // /2048
#pragma unroll
        for (int ks = 0; ks < 4; ks++) {
            uint2 aA = *(const uint2*)(Qh +  r0    *BSTR + ks*8 + 2*q4);
            uint2 aB = *(const uint2*)(Qh + (r0+8) *BSTR + ks*8 + 2*q4);
#pragma unroll
            for (int nb = 0; nb < 8; nb++) {
                uint2 bb = *(const uint2*)(Kh + (nb*8+g)*BSTR + ks*8 + 2*q4);
                mma16(s[nb], aA.x, aB.x, aA.y, aB.y, bb.x, bb.y);
            }
        }

        // ---- online softmax ----
        float mx0 = -3.0e38f, mx1 = -3.0e38f;
#pragma unroll
        for (int nb = 0; nb < 8; nb++) {
            mx0 = fmaxf(mx0, fmaxf(s[nb][0], s[nb][1]));
            mx1 = fmaxf(mx1, fmaxf(s[nb][2], s[nb][3]));
        }
        mx0 = fmaxf(mx0, __shfl_xor_sync(0xffffffffu, mx0, 1));
        mx0 = fmaxf(mx0, __shfl_xor_sync(0xffffffffu, mx0, 2));
        mx1 = fmaxf(mx1, __shfl_xor_sync(0xffffffffu, mx1, 1));
        mx1 = fmaxf(mx1, __shfl_xor_sync(0xffffffffu, mx1, 2));
        float mn0 = fmaxf(m0, mx0), mn1 = fmaxf(m1, mx1);
        float c0f = __expf(m0 - mn0), c1f = __expf(m1 - mn1);
        m0 = mn0; m1 = mn1;
        float sum0 = 0.f, sum1 = 0.f;
#pragma unroll
        for (int nb = 0; nb < 8; nb++) {
            s[nb][0] = __expf(s[nb][0] - mn0); sum0 += s[nb][0];
            s[nb][1] = __expf(s[nb][1] - mn0); sum0 += s[nb][1];
            s[nb][2] = __expf(s[nb][2] - mn1); sum1 += s[nb][2];
            s[nb][3] = __expf(s[nb][3] - mn1); sum1 += s[nb][3];
        }
        sum0 += __shfl_xor_sync(0xffffffffu, sum0, 1);
        sum0 += __shfl_xor_sync(0xffffffffu, sum0, 2);
        sum1 += __shfl_xor_sync(0xffffffffu, sum1, 1);
        sum1 += __shfl_xor_sync(0xffffffffu, sum1, 2);
        l0s = l0s*c0f + sum0;
        l1s = l1s*c1f + sum1;
#pragma unroll
        for (int nb = 0; nb < 8; nb++) {
            o[nb][0] *= c0f; o[nb][1] *= c0f;
            o[nb][2] *= c1f; o[nb][3] *= c1f;
        }

        // ---- O += P @ V directly from fragments ----
#pragma unroll
        for (int ks = 0; ks < 4; ks++) {
            uint32_t a0 = packh(s[2*ks  ][0], s[2*ks  ][1]);
            uint32_t a1 = packh(s[2*ks  ][2], s[2*ks  ][3]);
            uint32_t a2 = packh(s[2*ks+1][0], s[2*ks+1][1]);
            uint32_t a3 = packh(s[2*ks+1][2], s[2*ks+1][3]);
#pragma unroll
            for (int nb = 0; nb < 8; nb++) {
                uint2 bb = *(const uint2*)(Vt + (nb*8+g)*BSTR + ks*8 + 2*q4);
                mma16(o[nb], a0, a1, a2, a3, bb.x, bb.y);
            }
        }
        __syncthreads();
    }

    // ---- epilogue: normalize, write [B][C][N] ----
    float i0 = 1.f / l0s, i1 = 1.f / l1s;
    float* ob = outp + (size_t)b * 64 * N;
    const int q0 = qt * 128;
#pragma unroll
    for (int nb = 0; nb < 8; nb++) {
        int c = nb*8 + 2*q4;
        ob[(size_t) c   *N + q0 + r0    ] = o[nb][0]*i0;
        ob[(size_t)(c+1)*N + q0 + r0    ] = o[nb][1]*i0;
        ob[(size_t) c   *N + q0 + r0 + 8] = o[nb][2]*i1;
        ob[(size_t)(c+1)*N + q0 + r0 + 8] = o[nb][3]*i1;
    }
}

// ---------------- Stage 3: bilinear upsample + residual ----------------
__device__ __forceinline__ float bilin(const float* __restrict__ p, int hp,
                                       int y, int x, float inv_s) {
    float sy = (y + 0.5f)*inv_s - 0.5f;
    float sx = (x + 0.5f)*inv_s - 0.5f;
    float fy = floorf(sy), fx = floorf(sx);
    float wy = sy - fy, wx = sx - fx;
    int y0 = max((int)fy, 0), y1 = min((int)fy + 1, hp-1);
    int x0 = max((int)fx, 0), x1 = min((int)fx + 1, hp-1);
    float a = p[y0*hp + x0], b2 = p[y0*hp + x1];
    float c2 = p[y1*hp + x0], d2 = p[y1*hp + x1];
    return (a*(1.f-wx) + b2*wx)*(1.f-wy) + (c2*(1.f-wx) + d2*wx)*wy;
}

__global__ void __launch_bounds__(256) final_kernel(const float* __restrict__ x,
                                                    float* __restrict__ out) {
    int idx = blockIdx.x*256 + threadIdx.x;
    if (idx >= BB*CC*HH*WW) return;
    int xx = idx & 63, yy = (idx >> 6) & 63, bc = idx >> 12;
    float v = x[idx] + g_o1[idx];
    v += bilin(g_o2 + bc*1024, 32, yy, xx, 0.5f);
    v += bilin(g_o4 + bc*256,  16, yy, xx, 0.25f);
    out[idx] = v;
}

// ---------------- launch ----------------
extern "C" void kernel_launch(void* const* d_in, const int* in_sizes, int n_in,
                              void* d_out, int out_size) {
    const float* x = (const float*)d_in[0];
    const float* w = (const float*)d_in[1];
    float* out = (float*)d_out;

    cudaFuncSetAttribute(attn_mma<4096>, cudaFuncAttributeMaxDynamicSharedMemorySize, ATTN_SMEM);
    cudaFuncSetAttribute(attn_mma<1024>, cudaFuncAttributeMaxDynamicSharedMemorySize, ATTN_SMEM);
    cudaFuncSetAttribute(attn_mma<256>,  cudaFuncAttributeMaxDynamicSharedMemorySize, ATTN_SMEM);

    wtrans_kernel<<<(CC*9*CC + 255)/256, 256>>>(w);
    conv_kernel<<<dim3(16, 8), 512>>>(x);
    pool_kernel<1><<<dim3(128, 2, 8), 256>>>();
    pool_kernel<2><<<dim3(32, 2, 8), 256>>>();
    pool_kernel<4><<<dim3(8, 2, 8), 256>>>();
    split_kernel<4096><<<dim3(64, 8), 256>>>();
    split_kernel<1024><<<dim3(16, 8), 256>>>();
    split_kernel<256> <<<dim3(4, 8),  256>>>();
    attn_mma<4096><<<dim3(32, 8), 256, ATTN_SMEM>>>();
    attn_mma<1024><<<dim3(8, 8),  256, ATTN_SMEM>>>();
    attn_mma<256> <<<dim3(2, 8),  256, ATTN_SMEM>>>();
    final_kernel<<<(BB*CC*HH*WW + 255)/256, 256>>>(x, out);
}

// round 8
// speedup vs baseline: 1.8054x; 1.1169x over previous
#include <cuda_runtime.h>
#include <cuda_fp16.h>
#include <cstdint>
#include <math.h>

#define BB 8
#define CC 64
#define HH 64
#define WW 64

#define BSTR 40              // words per row in fp16x2 tiles
#define SEGW 2560            // 64 rows * BSTR words  (10KB)
#define KWORDS (3*SEGW)      // packed tile: Kh | Kl | Vt (30KB)

// ---------------- scratch (static device globals; no allocation) ----------------
__device__ float g_feat[BB*CC*HH*WW];      // [B][C][H][W]
__device__ float g_wt[CC*9*CC];            // transposed weights [ic][k][oc]
__device__ float g_f1[BB*4096*CC];         // [B][N][C] pooled features (f32)
__device__ float g_f2[BB*1024*CC];
__device__ float g_f4[BB*256*CC];
__device__ uint32_t g_p1[BB*64*KWORDS];    // packed fp16 tiles per scale
__device__ uint32_t g_p2[BB*16*KWORDS];
__device__ uint32_t g_p4[BB*4*KWORDS];
__device__ float g_o1[BB*CC*4096];         // attention outputs [B][C][n]
__device__ float g_o2[BB*CC*1024];
__device__ float g_o4[BB*CC*256];

__device__ __forceinline__ uint32_t packh(float lo, float hi) {  // word = {hi16, lo16}
    uint32_t r;
    asm("cvt.rn.f16x2.f32 %0, %1, %2;" : "=r"(r) : "f"(hi), "f"(lo));
    return r;
}
__device__ __forceinline__ int islot(int u) { return 2*(u & 3) + (u >> 2); }
__device__ __forceinline__ uint32_t smem_u32(const void* p) {
    uint32_t a;
    asm("{ .reg .u64 t; cvta.to.shared.u64 t, %1; cvt.u32.u64 %0, t; }" : "=r"(a) : "l"(p));
    return a;
}
#define CP16(dst, src) asm volatile("cp.async.cg.shared.global [%0], [%1], 16;" :: "r"(dst), "l"(src))
#define CP_COMMIT()    asm volatile("cp.async.commit_group;" ::: "memory")
#define CP_WAIT1()     asm volatile("cp.async.wait_group 1;" ::: "memory")
#define HEX2(x)        asm("ex2.approx.f16x2 %0, %0;" : "+r"(x))

// m16n8k16 fp16 MMA, row.col, f32 accumulate-in-place
__device__ __forceinline__ void mma16(float* d, uint32_t a0, uint32_t a1, uint32_t a2,
                                      uint32_t a3, uint32_t b0, uint32_t b1) {
    asm volatile("mma.sync.aligned.m16n8k16.row.col.f32.f16.f16.f32 "
        "{%0,%1,%2,%3}, {%4,%5,%6,%7}, {%8,%9}, {%0,%1,%2,%3};"
        : "+f"(d[0]), "+f"(d[1]), "+f"(d[2]), "+f"(d[3])
        : "r"(a0), "r"(a1), "r"(a2), "r"(a3), "r"(b0), "r"(b1));
}

// ---------------- Stage 0: weight transpose ----------------
__global__ void __launch_bounds__(256) wtrans_kernel(const float* __restrict__ w) {
    int i = blockIdx.x*256 + threadIdx.x;
    if (i >= CC*9*CC) return;
    int oc = i & 63, k = (i >> 6) % 9, ic = i / 576;
    g_wt[i] = w[oc*576 + ic*9 + k];
}

// ---------------- Stage 1: 3x3 conv + depthwise Laplacian ----------------
__global__ void __launch_bounds__(512) conv_kernel(const float* __restrict__ x) {
    __shared__ float xs[18][18];
    __shared__ float4 ws4[9*16];
    const int tile = blockIdx.x;
    const int b = blockIdx.y;
    const int y0 = (tile >> 2) << 4;
    const int x0 = (tile & 3) << 4;
    const int tid = threadIdx.x;
    const int px = tid & 255;
    const int half = tid >> 8;
    const int pxx = px & 15, py = px >> 4;
    float acc[32];
#pragma unroll
    for (int i = 0; i < 32; i++) acc[i] = 0.f;
    const float* xb = x + b*CC*HH*WW;
    for (int ic = 0; ic < 64; ic++) {
        if (tid < 18*18) {
            int yy = tid / 18, xx = tid % 18;
            int gy = y0 + yy - 1, gx = x0 + xx - 1;
            float v = 0.f;
            if (gy >= 0 && gy < HH && gx >= 0 && gx < WW)
                v = xb[ic*HH*WW + gy*WW + gx];
            xs[yy][xx] = v;
        }
        if (tid < 144)
            ws4[tid] = ((const float4*)(g_wt + ic*576))[tid];
        __syncthreads();
        float xv[9];
#pragma unroll
        for (int dy = 0; dy < 3; dy++)
#pragma unroll
            for (int dx = 0; dx < 3; dx++)
                xv[dy*3+dx] = xs[py+dy][pxx+dx];
#pragma unroll
        for (int k = 0; k < 9; k++) {
            float xk = xv[k];
#pragma unroll
            for (int g8 = 0; g8 < 8; g8++) {
                float4 wv = ws4[k*16 + half*8 + g8];
                acc[g8*4+0] = fmaf(xk, wv.x, acc[g8*4+0]);
                acc[g8*4+1] = fmaf(xk, wv.y, acc[g8*4+1]);
                acc[g8*4+2] = fmaf(xk, wv.z, acc[g8*4+2]);
                acc[g8*4+3] = fmaf(xk, wv.w, acc[g8*4+3]);
            }
        }
        if ((ic >> 5) == half) {
            float lap = xv[1] + xv[3] + xv[5] + xv[7] - 4.f*xv[4];
            acc[ic & 31] += lap;
        }
        __syncthreads();
    }
    float* fb = g_feat + b*CC*HH*WW + (y0+py)*WW + x0 + pxx;
#pragma unroll
    for (int j = 0; j < 32; j++)
        fb[(half*32 + j)*HH*WW] = acc[j];
}

// ---------------- Stage 2a: pool + transpose to [B][N][C] ----------------
template<int S>
__global__ void __launch_bounds__(256) pool_kernel() {
    constexpr int WP = WW / S;
    constexpr int N  = (HH/S) * (WW/S);
    float* out = (S == 1) ? g_f1 : (S == 2) ? g_f2 : g_f4;
    __shared__ float tile[32][33];
    const int b  = blockIdx.z;
    const int c0 = blockIdx.y * 32;
    const int n0 = blockIdx.x * 32;
    const int tid = threadIdx.x;
    const int tx = tid & 31, ty = tid >> 5;
    for (int ci = ty; ci < 32; ci += 8) {
        int n = n0 + tx;
        int ny = n / WP, nx = n % WP;
        const float* fp = g_feat + ((b*CC + c0 + ci)*HH + ny*S)*WW + nx*S;
        float s = 0.f;
#pragma unroll
        for (int dy = 0; dy < S; dy++)
#pragma unroll
            for (int dx = 0; dx < S; dx++)
                s += fp[dy*WW + dx];
        tile[ci][tx] = s * (1.f/(S*S));
    }
    __syncthreads();
    for (int ni = ty; ni < 32; ni += 8)
        out[(b*N + n0 + ni)*CC + c0 + tx] = tile[tx][ni];
}

// ---------------- Stage 2a': split/pack once, all scales fused ----------------
__global__ void __launch_bounds__(256) split_fused() {
    const int t = blockIdx.x;
    const int b = blockIdx.y;
    const float* f; uint32_t* gpack; int tt, N;
    if (t < 64)      { f = g_f1; gpack = g_p1; tt = t;      N = 4096; }
    else if (t < 80) { f = g_f2; gpack = g_p2; tt = t - 64; N = 1024; }
    else             { f = g_f4; gpack = g_p4; tt = t - 80; N = 256;  }
    const float* fb = f + ((size_t)b*N + tt*64) * 64;
    uint32_t* gp = gpack + ((size_t)b*(N/64) + tt) * KWORDS;
    const int tid = threadIdx.x;
#pragma unroll
    for (int j = 0; j < 8; j++) {
        int wi = j*256 + tid;
        int r = wi >> 5, u = wi & 31;
        float a = fb[r*64 + 2*u];
        float c = fb[r*64 + 2*u + 1];
        uint32_t h = packh(a, c);
        float2 fh = __half22float2(*(const __half2*)&h);
        uint32_t l = packh((a - fh.x)*2048.f, (c - fh.y)*2048.f);
        int slot = r*BSTR + (u >> 3)*8 + islot(u & 7);
        gp[slot]        = h;
        gp[SEGW + slot] = l;
    }
#pragma unroll
    for (int j = 0; j < 8; j++) {
        int wi = j*256 + tid;
        int ch = wi >> 5, lwv = wi & 31;
        float a = fb[(2*lwv    )*64 + ch];
        float c = fb[(2*lwv + 1)*64 + ch];
        gp[2*SEGW + ch*BSTR + (lwv >> 3)*8 + islot(lwv & 7)] = packh(a, c);
    }
}

// ---------------- Stage 2b: fused fp16-split flash attention, all scales ----------------
// CTA: 128 queries, 256 threads (8 warps), 64-key tiles, cp.async double buffer.
// grid.x: [0,32)=scale1, [32,40)=scale2, [40,42)=scale4.
// exp via ex2.approx.f16x2; row-sum l via ones-column MMA (constant B fragment).
#define Q_WORDS 5120
#define ATTN_SMEM ((2*Q_WORDS + 2*KWORDS) * 4)

__global__ void __launch_bounds__(256, 2) attn_fused() {
    const int qtsel = blockIdx.x;
    const int b = blockIdx.y;
    int N, qt;
    const uint32_t* gpack;
    float* outp;
    if (qtsel < 32)      { N = 4096; qt = qtsel;      gpack = g_p1; outp = g_o1; }
    else if (qtsel < 40) { N = 1024; qt = qtsel - 32; gpack = g_p2; outp = g_o2; }
    else                 { N = 256;  qt = qtsel - 40; gpack = g_p4; outp = g_o4; }
    const int T = N >> 6;

    extern __shared__ uint32_t smw[];
    uint32_t* Qh = smw;
    uint32_t* Ql = smw + Q_WORDS;
    uint32_t* KB[2] = { smw + 2*Q_WORDS, smw + 2*Q_WORDS + KWORDS };

    const int tid  = threadIdx.x;
    const int w    = tid >> 5;
    const int lane = tid & 31;
    const int g    = lane >> 2;
    const int q4   = lane & 3;
    const int r0   = w*16 + g;
    const uint32_t* gb = gpack + (size_t)b*T*KWORDS;
    const uint32_t sb = smem_u32(smw);
    const uint32_t bones = (g == 0) ? 0x3C003C00u : 0u;   // fp16 ones col for l-sum

    // group 0: Q (Kh/Kl of tiles 2qt, 2qt+1) + K tile 0
#pragma unroll
    for (int j = 0; j < 10; j++) {
        int i = j*256 + tid;
        int seg = i / 640;
        int s = seg >> 1, p = seg & 1;
        int fo = (i - seg*640) * 4;
        const uint32_t* src = gb + (size_t)(2*qt + p)*KWORDS + s*SEGW + fo;
        CP16(sb + (s*Q_WORDS + p*SEGW + fo)*4, src);
    }
    {
        const uint32_t* src = gb;
#pragma unroll
        for (int j = 0; j < 8; j++) {
            int i = j*256 + tid;
            if (i < 1920) CP16(sb + (2*Q_WORDS + i*4)*4, src + i*4);
        }
    }
    CP_COMMIT();

    float m0 = -3.0e38f, m1 = -3.0e38f;
    float d_l[4] = {0.f, 0.f, 0.f, 0.f};
    float o[8][4];
#pragma unroll
    for (int nb = 0; nb < 8; nb++)
#pragma unroll
        for (int j = 0; j < 4; j++) o[nb][j] = 0.f;

    for (int kb = 0; kb < T; kb++) {
        {
            int nxt = (kb + 1 < T) ? kb + 1 : T - 1;
            const uint32_t* src = gb + (size_t)nxt*KWORDS;
            uint32_t dstb = sb + (2*Q_WORDS + ((kb + 1) & 1)*KWORDS)*4;
#pragma unroll
            for (int j = 0; j < 8; j++) {
                int i = j*256 + tid;
                if (i < 1920) CP16(dstb + i*16, src + i*4);
            }
            CP_COMMIT();
        }
        CP_WAIT1();
        __syncthreads();

        const uint32_t* Kh = KB[kb & 1];
        const uint32_t* Kl = Kh + SEGW;
        const uint32_t* Vt = Kh + 2*SEGW;

        // ---- S: corrections (scaled x2048) then /2048 then exact hh ----
        float s[8][4];
#pragma unroll
        for (int nb = 0; nb < 8; nb++)
#pragma unroll
            for (int j = 0; j < 4; j++) s[nb][j] = 0.f;

#pragma unroll
        for (int pass = 0; pass < 2; pass++) {
            const uint32_t* Ab = pass ? Ql : Qh;
            const uint32_t* Bb = pass ? Kh : Kl;
#pragma unroll
            for (int ks = 0; ks < 4; ks++) {
                uint2 aA = *(const uint2*)(Ab +  r0    *BSTR + ks*8 + 2*q4);
                uint2 aB = *(const uint2*)(Ab + (r0+8) *BSTR + ks*8 + 2*q4);
#pragma unroll
                for (int nb = 0; nb < 8; nb++) {
                    uint2 bb = *(const uint2*)(Bb + (nb*8+g)*BSTR + ks*8 + 2*q4);
                    mma16(s[nb], aA.x, aB.x, aA.y, aB.y, bb.x, bb.y);
                }
            }
        }
#pragma unroll
        for (int nb = 0; nb < 8; nb++)
#pragma unroll
            for (int j = 0; j < 4; j++) s[nb][j] *= 4.8828125e-4f;   // /2048
#pragma unroll
        for (int ks = 0; ks < 4; ks++) {
            uint2 aA = *(const uint2*)(Qh +  r0    *BSTR + ks*8 + 2*q4);
            uint2 aB = *(const uint2*)(Qh + (r0+8) *BSTR + ks*8 + 2*q4);
#pragma unroll
            for (int nb = 0; nb < 8; nb++) {
                uint2 bb = *(const uint2*)(Kh + (nb*8+g)*BSTR + ks*8 + 2*q4);
                mma16(s[nb], aA.x, aB.x, aA.y, aB.y, bb.x, bb.y);
            }
        }

        // ---- online max + rescale ----
        float mx0 = -3.0e38f, mx1 = -3.0e38f;
#pragma unroll
        for (int nb = 0; nb < 8; nb++) {
            mx0 = fmaxf(mx0, fmaxf(s[nb][0], s[nb][1]));
            mx1 = fmaxf(mx1, fmaxf(s[nb][2], s[nb][3]));
        }
        mx0 = fmaxf(mx0, __shfl_xor_sync(0xffffffffu, mx0, 1));
        mx0 = fmaxf(mx0, __shfl_xor_sync(0xffffffffu, mx0, 2));
        mx1 = fmaxf(mx1, __shfl_xor_sync(0xffffffffu, mx1, 1));
        mx1 = fmaxf(mx1, __shfl_xor_sync(0xffffffffu, mx1, 2));
        float mn0 = fmaxf(m0, mx0), mn1 = fmaxf(m1, mx1);
        float c0f = __expf(m0 - mn0), c1f = __expf(m1 - mn1);
        m0 = mn0; m1 = mn1;
        d_l[0] *= c0f; d_l[1] *= c0f; d_l[2] *= c1f; d_l[3] *= c1f;
#pragma unroll
        for (int nb = 0; nb < 8; nb++) {
            o[nb][0] *= c0f; o[nb][1] *= c0f;
            o[nb][2] *= c1f; o[nb][3] *= c1f;
        }

        // ---- P = exp2((s - m)·log2e) in f16x2; l via ones-MMA; O += P·V ----
        const float L2E = 1.4426950408889634f;
        float ml0 = mn0 * L2E, ml1 = mn1 * L2E;
#pragma unroll
        for (int ks = 0; ks < 4; ks++) {
            float t0 = fmaf(s[2*ks  ][0], L2E, -ml0);
            float t1 = fmaf(s[2*ks  ][1], L2E, -ml0);
            float t2 = fmaf(s[2*ks  ][2], L2E, -ml1);
            float t3 = fmaf(s[2*ks  ][3], L2E, -ml1);
            uint32_t a0 = packh(t0, t1);
            uint32_t a1 = packh(t2, t3);
            t0 = fmaf(s[2*ks+1][0], L2E, -ml0);
            t1 = fmaf(s[2*ks+1][1], L2E, -ml0);
            t2 = fmaf(s[2*ks+1][2], L2E, -ml1);
            t3 = fmaf(s[2*ks+1][3], L2E, -ml1);
            uint32_t a2 = packh(t0, t1);
            uint32_t a3 = packh(t2, t3);
            HEX2(a0); HEX2(a1); HEX2(a2); HEX2(a3);
            mma16(d_l, a0, a1, a2, a3, bones, bones);
#pragma unroll
            for (int nb = 0; nb < 8; nb++) {
                uint2 bb = *(const uint2*)(Vt + (nb*8+g)*BSTR + ks*8 + 2*q4);
                mma16(o[nb], a0, a1, a2, a3, bb.x, bb.y);
            }
        }
        __syncthreads();
    }

    // ---- epilogue: l lives in col 0 (q4==0 lanes); broadcast, normalize, write ----
    float lr0 = __shfl_sync(0xffffffffu, d_l[0], lane & 28);
    float lr1 = __shfl_sync(0xffffffffu, d_l[2], lane & 28);
    float i0 = 1.f / lr0, i1 = 1.f / lr1;
    float* ob = outp + (size_t)b * 64 * N;
    const int q0 = qt * 128;
#pragma unroll
    for (int nb = 0; nb < 8; nb++) {
        int c = nb*8 + 2*q4;
        ob[(size_t) c   *N + q0 + r0    ] = o[nb][0]*i0;
        ob[(size_t)(c+1)*N + q0 + r0    ] = o[nb][1]*i0;
        ob[(size_t) c   *N + q0 + r0 + 8] = o[nb][2]*i1;
        ob[(size_t)(c+1)*N + q0 + r0 + 8] = o[nb][3]*i1;
    }
}

// ---------------- Stage 3: bilinear upsample + residual ----------------
__device__ __forceinline__ float bilin(const float* __restrict__ p, int hp,
                                       int y, int x, float inv_s) {
    float sy = (y + 0.5f)*inv_s - 0.5f;
    float sx = (x + 0.5f)*inv_s - 0.5f;
    float fy = floorf(sy), fx = floorf(sx);
    float wy = sy - fy, wx = sx - fx;
    int y0 = max((int)fy, 0), y1 = min((int)fy + 1, hp-1);
    int x0 = max((int)fx, 0), x1 = min((int)fx + 1, hp-1);
    float a = p[y0*hp + x0], b2 = p[y0*hp + x1];
    float c2 = p[y1*hp + x0], d2 = p[y1*hp + x1];
    return (a*(1.f-wx) + b2*wx)*(1.f-wy) + (c2*(1.f-wx) + d2*wx)*wy;
}

__global__ void __launch_bounds__(256) final_kernel(const float* __restrict__ x,
                                                    float* __restrict__ out) {
    int idx = blockIdx.x*256 + threadIdx.x;
    if (idx >= BB*CC*HH*WW) return;
    int xx = idx & 63, yy = (idx >> 6) & 63, bc = idx >> 12;
    float v = x[idx] + g_o1[idx];
    v += bilin(g_o2 + bc*1024, 32, yy, xx, 0.5f);
    v += bilin(g_o4 + bc*256,  16, yy, xx, 0.25f);
    out[idx] = v;
}

// ---------------- launch ----------------
extern "C" void kernel_launch(void* const* d_in, const int* in_sizes, int n_in,
                              void* d_out, int out_size) {
    const float* x = (const float*)d_in[0];
    const float* w = (const float*)d_in[1];
    float* out = (float*)d_out;

    cudaFuncSetAttribute(attn_fused, cudaFuncAttributeMaxDynamicSharedMemorySize, ATTN_SMEM);

    wtrans_kernel<<<(CC*9*CC + 255)/256, 256>>>(w);
    conv_kernel<<<dim3(16, 8), 512>>>(x);
    pool_kernel<1><<<dim3(128, 2, 8), 256>>>();
    pool_kernel<2><<<dim3(32, 2, 8), 256>>>();
    pool_kernel<4><<<dim3(8, 2, 8), 256>>>();
    split_fused<<<dim3(84, 8), 256>>>();
    attn_fused<<<dim3(42, 8), 256, ATTN_SMEM>>>();
    final_kernel<<<(BB*CC*HH*WW + 255)/256, 256>>>(x, out);
}

// round 9
// speedup vs baseline: 2.1151x; 1.1716x over previous
#include <cuda_runtime.h>
#include <cuda_fp16.h>
#include <cstdint>
#include <math.h>

#define BB 8
#define CC 64
#define HH 64
#define WW 64

#define BSTR 40              // words per row in fp16x2 tiles
#define SEGW 2560            // 64 rows * BSTR words  (10KB)
#define KWORDS (3*SEGW)      // packed tile: Kh | Kl | Vt (30KB)

// ---------------- scratch (static device globals; no allocation) ----------------
__device__ float g_feat[BB*CC*HH*WW];      // [B][C][H][W]
__device__ float g_wt[CC*9*CC];            // transposed weights [ic][k][oc]
__device__ uint32_t g_p1[BB*64*KWORDS];    // packed fp16 tiles per scale
__device__ uint32_t g_p2[BB*16*KWORDS];
__device__ uint32_t g_p4[BB*4*KWORDS];
__device__ float g_o1[BB*CC*4096];         // attention outputs [B][C][n]
__device__ float g_o2[BB*CC*1024];
__device__ float g_o4[BB*CC*256];

__device__ __forceinline__ uint32_t packh(float lo, float hi) {  // word = {hi16, lo16}
    uint32_t r;
    asm("cvt.rn.f16x2.f32 %0, %1, %2;" : "=r"(r) : "f"(hi), "f"(lo));
    return r;
}
__device__ __forceinline__ int islot(int u) { return 2*(u & 3) + (u >> 2); }
__device__ __forceinline__ uint32_t smem_u32(const void* p) {
    uint32_t a;
    asm("{ .reg .u64 t; cvta.to.shared.u64 t, %1; cvt.u32.u64 %0, t; }" : "=r"(a) : "l"(p));
    return a;
}
#define CP16(dst, src) asm volatile("cp.async.cg.shared.global [%0], [%1], 16;" :: "r"(dst), "l"(src))
#define CP_COMMIT()    asm volatile("cp.async.commit_group;" ::: "memory")
#define CP_WAIT1()     asm volatile("cp.async.wait_group 1;" ::: "memory")
#define CP_WAIT0()     asm volatile("cp.async.wait_group 0;" ::: "memory")
#define HEX2(x)        asm("ex2.approx.f16x2 %0, %0;" : "+r"(x))

// m16n8k16 fp16 MMA, row.col, f32 accumulate-in-place
__device__ __forceinline__ void mma16(float* d, uint32_t a0, uint32_t a1, uint32_t a2,
                                      uint32_t a3, uint32_t b0, uint32_t b1) {
    asm volatile("mma.sync.aligned.m16n8k16.row.col.f32.f16.f16.f32 "
        "{%0,%1,%2,%3}, {%4,%5,%6,%7}, {%8,%9}, {%0,%1,%2,%3};"
        : "+f"(d[0]), "+f"(d[1]), "+f"(d[2]), "+f"(d[3])
        : "r"(a0), "r"(a1), "r"(a2), "r"(a3), "r"(b0), "r"(b1));
}

// ---------------- Stage 0: weight transpose ----------------
__global__ void __launch_bounds__(256) wtrans_kernel(const float* __restrict__ w) {
    int i = blockIdx.x*256 + threadIdx.x;
    if (i >= CC*9*CC) return;
    int oc = i & 63, k = (i >> 6) % 9, ic = i / 576;
    g_wt[i] = w[oc*576 + ic*9 + k];
}

// ---------------- Stage 1: 3x3 conv + depthwise Laplacian ----------------
__global__ void __launch_bounds__(512) conv_kernel(const float* __restrict__ x) {
    __shared__ float xs[18][18];
    __shared__ float4 ws4[9*16];
    const int tile = blockIdx.x;
    const int b = blockIdx.y;
    const int y0 = (tile >> 2) << 4;
    const int x0 = (tile & 3) << 4;
    const int tid = threadIdx.x;
    const int px = tid & 255;
    const int half = tid >> 8;
    const int pxx = px & 15, py = px >> 4;
    float acc[32];
#pragma unroll
    for (int i = 0; i < 32; i++) acc[i] = 0.f;
    const float* xb = x + b*CC*HH*WW;
    for (int ic = 0; ic < 64; ic++) {
        if (tid < 18*18) {
            int yy = tid / 18, xx = tid % 18;
            int gy = y0 + yy - 1, gx = x0 + xx - 1;
            float v = 0.f;
            if (gy >= 0 && gy < HH && gx >= 0 && gx < WW)
                v = xb[ic*HH*WW + gy*WW + gx];
            xs[yy][xx] = v;
        }
        if (tid < 144)
            ws4[tid] = ((const float4*)(g_wt + ic*576))[tid];
        __syncthreads();
        float xv[9];
#pragma unroll
        for (int dy = 0; dy < 3; dy++)
#pragma unroll
            for (int dx = 0; dx < 3; dx++)
                xv[dy*3+dx] = xs[py+dy][pxx+dx];
#pragma unroll
        for (int k = 0; k < 9; k++) {
            float xk = xv[k];
#pragma unroll
            for (int g8 = 0; g8 < 8; g8++) {
                float4 wv = ws4[k*16 + half*8 + g8];
                acc[g8*4+0] = fmaf(xk, wv.x, acc[g8*4+0]);
                acc[g8*4+1] = fmaf(xk, wv.y, acc[g8*4+1]);
                acc[g8*4+2] = fmaf(xk, wv.z, acc[g8*4+2]);
                acc[g8*4+3] = fmaf(xk, wv.w, acc[g8*4+3]);
            }
        }
        if ((ic >> 5) == half) {
            float lap = xv[1] + xv[3] + xv[5] + xv[7] - 4.f*xv[4];
            acc[ic & 31] += lap;
        }
        __syncthreads();
    }
    float* fb = g_feat + b*CC*HH*WW + (y0+py)*WW + x0 + pxx;
#pragma unroll
    for (int j = 0; j < 32; j++)
        fb[(half*32 + j)*HH*WW] = acc[j];
}

// ---------------- Stage 2a: fused pool + split/pack (reads g_feat, writes packs) ----------------
__global__ void __launch_bounds__(256) poolpack_kernel() {
    const int t = blockIdx.x;
    const int b = blockIdx.y;
    int S, tt, N; uint32_t* gpack;
    if (t < 64)      { S = 1; tt = t;      gpack = g_p1; N = 4096; }
    else if (t < 80) { S = 2; tt = t - 64; gpack = g_p2; N = 1024; }
    else             { S = 4; tt = t - 80; gpack = g_p4; N = 256;  }
    const int WP = 64 / S;
    const float inv = 1.f / (float)(S*S);
    __shared__ float tile[64][65];
    const float* fb = g_feat + (size_t)b*CC*HH*WW;
    const int tid = threadIdx.x;

    // pool into smem: tile[key][ch]
    for (int i = tid; i < 4096; i += 256) {
        int ch = i >> 6, key = i & 63;
        int n = tt*64 + key;
        int ny = n / WP, nx = n % WP;
        const float* p = fb + ch*4096 + (ny*S)*64 + nx*S;
        float s = 0.f;
        for (int dy = 0; dy < S; dy++)
            for (int dx = 0; dx < S; dx++)
                s += p[dy*64 + dx];
        tile[key][ch] = s * inv;
    }
    __syncthreads();

    uint32_t* gp = gpack + ((size_t)b*(N >> 6) + tt) * KWORDS;
    // Kh / Kl segments
#pragma unroll
    for (int j = 0; j < 8; j++) {
        int wi = j*256 + tid;
        int r = wi >> 5, u = wi & 31;
        float a = tile[r][2*u];
        float c = tile[r][2*u + 1];
        uint32_t h = packh(a, c);
        float2 fh = __half22float2(*(const __half2*)&h);
        uint32_t l = packh((a - fh.x)*2048.f, (c - fh.y)*2048.f);
        int slot = r*BSTR + (u >> 3)*8 + islot(u & 7);
        gp[slot]        = h;
        gp[SEGW + slot] = l;
    }
    // Vt segment
#pragma unroll
    for (int j = 0; j < 8; j++) {
        int wi = j*256 + tid;
        int ch = wi >> 5, lwv = wi & 31;
        float a = tile[2*lwv    ][ch];
        float c = tile[2*lwv + 1][ch];
        gp[2*SEGW + ch*BSTR + (lwv >> 3)*8 + islot(lwv & 7)] = packh(a, c);
    }
}

// ---------------- Stage 2b: fused flash attention, reg-Q + 3-buffer pipeline ----------------
// CTA: 128 queries, 256 threads (8 warps). smem: Ql[5120w] + 3 K buffers[7680w] = 110KB, 2 CTAs/SM.
// Qh A-fragments live in registers (loaded once). One __syncthreads per tile.
#define QLW 5120
#define ATTN_SMEM ((QLW + 3*KWORDS) * 4)

__global__ void __launch_bounds__(256, 2) attn_fused() {
    const int qtsel = blockIdx.x;
    const int b = blockIdx.y;
    int N, qt;
    const uint32_t* gpack;
    float* outp;
    if (qtsel < 32)      { N = 4096; qt = qtsel;      gpack = g_p1; outp = g_o1; }
    else if (qtsel < 40) { N = 1024; qt = qtsel - 32; gpack = g_p2; outp = g_o2; }
    else                 { N = 256;  qt = qtsel - 40; gpack = g_p4; outp = g_o4; }
    const int T = N >> 6;

    extern __shared__ uint32_t smw[];
    uint32_t* Ql = smw;                       // [5120]
    uint32_t* KB0 = smw + QLW;                // 3 K buffers

    const int tid  = threadIdx.x;
    const int w    = tid >> 5;
    const int lane = tid & 31;
    const int g    = lane >> 2;
    const int q4   = lane & 3;
    const int r0   = w*16 + g;
    const uint32_t* gb = gpack + (size_t)b*T*KWORDS;
    const uint32_t sb = smem_u32(smw);
    const uint32_t bones = (g == 0) ? 0x3C003C00u : 0u;   // fp16 ones col for l-sum

    // ---- preload: Qh -> KB0 (staging), Ql -> Ql region ----
#pragma unroll
    for (int j = 0; j < 10; j++) {
        int i = j*256 + tid;                 // 2560 float4
        int seg = i / 640;                   // 0:Qh p0 1:Qh p1 2:Ql p0 3:Ql p1
        int s = seg >> 1, p = seg & 1;
        int fo = (i - seg*640) * 4;
        const uint32_t* src = gb + (size_t)(2*qt + p)*KWORDS + s*SEGW + fo;
        int dst = (s ? 0 : QLW) + p*SEGW + fo;
        CP16(sb + dst*4, src);
    }
    CP_COMMIT();
    CP_WAIT0();
    __syncthreads();

    // extract Qh A-fragments to registers
    uint2 qA[4], qB[4];
#pragma unroll
    for (int ks = 0; ks < 4; ks++) {
        qA[ks] = *(const uint2*)(KB0 +  r0    *BSTR + ks*8 + 2*q4);
        qB[ks] = *(const uint2*)(KB0 + (r0+8) *BSTR + ks*8 + 2*q4);
    }
    __syncthreads();   // done reading KB0 before tile0 overwrites it

    // issue tiles 0 and 1
#pragma unroll
    for (int p = 0; p < 2; p++) {
        const uint32_t* src = gb + (size_t)p*KWORDS;
        uint32_t dstb = sb + (QLW + p*KWORDS)*4;
#pragma unroll
        for (int j = 0; j < 8; j++) {
            int i = j*256 + tid;
            if (i < 1920) CP16(dstb + i*16, src + i*4);
        }
        CP_COMMIT();
    }

    float m0 = -3.0e38f, m1 = -3.0e38f;
    float d_l[4] = {0.f, 0.f, 0.f, 0.f};
    float o[8][4];
#pragma unroll
    for (int nb = 0; nb < 8; nb++)
#pragma unroll
        for (int j = 0; j < 4; j++) o[nb][j] = 0.f;

    int buf = 0;
    for (int kb = 0; kb < T; kb++) {
        if (kb == T - 1) CP_WAIT0(); else CP_WAIT1();
        __syncthreads();

        // prefetch tile kb+2 into buffer (kb+2)%3 (safe: last read at iter kb-1)
        if (kb + 2 < T) {
            int nb3 = buf + 2; if (nb3 >= 3) nb3 -= 3;
            const uint32_t* src = gb + (size_t)(kb + 2)*KWORDS;
            uint32_t dstb = sb + (QLW + nb3*KWORDS)*4;
#pragma unroll
            for (int j = 0; j < 8; j++) {
                int i = j*256 + tid;
                if (i < 1920) CP16(dstb + i*16, src + i*4);
            }
            CP_COMMIT();
        }

        const uint32_t* Kh = KB0 + buf*KWORDS;
        const uint32_t* Kl = Kh + SEGW;
        const uint32_t* Vt = Kh + 2*SEGW;

        // ---- S: corrections (scaled x2048) then /2048 then exact hh ----
        float s[8][4];
#pragma unroll
        for (int nb = 0; nb < 8; nb++)
#pragma unroll
            for (int j = 0; j < 4; j++) s[nb][j] = 0.f;

        // pass 0: Qh(regs) * Kl
#pragma unroll
        for (int ks = 0; ks < 4; ks++) {
#pragma unroll
            for (int nb = 0; nb < 8; nb++) {
                uint2 bb = *(const uint2*)(Kl + (nb*8+g)*BSTR + ks*8 + 2*q4);
                mma16(s[nb], qA[ks].x, qB[ks].x, qA[ks].y, qB[ks].y, bb.x, bb.y);
            }
        }
        // pass 1: Ql(smem) * Kh
#pragma unroll
        for (int ks = 0; ks < 4; ks++) {
            uint2 aA = *(const uint2*)(Ql +  r0    *BSTR + ks*8 + 2*q4);
            uint2 aB = *(const uint2*)(Ql + (r0+8) *BSTR + ks*8 + 2*q4);
#pragma unroll
            for (int nb = 0; nb < 8; nb++) {
                uint2 bb = *(const uint2*)(Kh + (nb*8+g)*BSTR + ks*8 + 2*q4);
                mma16(s[nb], aA.x, aB.x, aA.y, aB.y, bb.x, bb.y);
            }
        }
#pragma unroll
        for (int nb = 0; nb < 8; nb++)
#pragma unroll
            for (int j = 0; j < 4; j++) s[nb][j] *= 4.8828125e-4f;   // /2048
        // pass 2: exact hh
#pragma unroll
        for (int ks = 0; ks < 4; ks++) {
#pragma unroll
            for (int nb = 0; nb < 8; nb++) {
                uint2 bb = *(const uint2*)(Kh + (nb*8+g)*BSTR + ks*8 + 2*q4);
                mma16(s[nb], qA[ks].x, qB[ks].x, qA[ks].y, qB[ks].y, bb.x, bb.y);
            }
        }

        // ---- online max + rescale ----
        float mx0 = -3.0e38f, mx1 = -3.0e38f;
#pragma unroll
        for (int nb = 0; nb < 8; nb++) {
            mx0 = fmaxf(mx0, fmaxf(s[nb][0], s[nb][1]));
            mx1 = fmaxf(mx1, fmaxf(s[nb][2], s[nb][3]));
        }
        mx0 = fmaxf(mx0, __shfl_xor_sync(0xffffffffu, mx0, 1));
        mx0 = fmaxf(mx0, __shfl_xor_sync(0xffffffffu, mx0, 2));
        mx1 = fmaxf(mx1, __shfl_xor_sync(0xffffffffu, mx1, 1));
        mx1 = fmaxf(mx1, __shfl_xor_sync(0xffffffffu, mx1, 2));
        float mn0 = fmaxf(m0, mx0), mn1 = fmaxf(m1, mx1);
        float c0f = __expf(m0 - mn0), c1f = __expf(m1 - mn1);
        m0 = mn0; m1 = mn1;
        d_l[0] *= c0f; d_l[1] *= c0f; d_l[2] *= c1f; d_l[3] *= c1f;
#pragma unroll
        for (int nb = 0; nb < 8; nb++) {
            o[nb][0] *= c0f; o[nb][1] *= c0f;
            o[nb][2] *= c1f; o[nb][3] *= c1f;
        }

        // ---- P = exp2(s*log2e - m*log2e) in f16x2; l via ones-MMA; O += P*V ----
        const float L2E = 1.4426950408889634f;
        float ml0 = mn0 * L2E, ml1 = mn1 * L2E;
#pragma unroll
        for (int ks = 0; ks < 4; ks++) {
            float t0 = fmaf(s[2*ks  ][0], L2E, -ml0);
            float t1 = fmaf(s[2*ks  ][1], L2E, -ml0);
            float t2 = fmaf(s[2*ks  ][2], L2E, -ml1);
            float t3 = fmaf(s[2*ks  ][3], L2E, -ml1);
            uint32_t a0 = packh(t0, t1);
            uint32_t a1 = packh(t2, t3);
            t0 = fmaf(s[2*ks+1][0], L2E, -ml0);
            t1 = fmaf(s[2*ks+1][1], L2E, -ml0);
            t2 = fmaf(s[2*ks+1][2], L2E, -ml1);
            t3 = fmaf(s[2*ks+1][3], L2E, -ml1);
            uint32_t a2 = packh(t0, t1);
            uint32_t a3 = packh(t2, t3);
            HEX2(a0); HEX2(a1); HEX2(a2); HEX2(a3);
            mma16(d_l, a0, a1, a2, a3, bones, bones);
#pragma unroll
            for (int nb = 0; nb < 8; nb++) {
                uint2 bb = *(const uint2*)(Vt + (nb*8+g)*BSTR + ks*8 + 2*q4);
                mma16(o[nb], a0, a1, a2, a3, bb.x, bb.y);
            }
        }
        buf++; if (buf == 3) buf = 0;
    }

    // ---- epilogue: l in col 0 (q4==0 lanes); broadcast, normalize, write ----
    float lr0 = __shfl_sync(0xffffffffu, d_l[0], lane & 28);
    float lr1 = __shfl_sync(0xffffffffu, d_l[2], lane & 28);
    float i0 = 1.f / lr0, i1 = 1.f / lr1;
    float* ob = outp + (size_t)b * 64 * N;
    const int q0 = qt * 128;
#pragma unroll
    for (int nb = 0; nb < 8; nb++) {
        int c = nb*8 + 2*q4;
        ob[(size_t) c   *N + q0 + r0    ] = o[nb][0]*i0;
        ob[(size_t)(c+1)*N + q0 + r0    ] = o[nb][1]*i0;
        ob[(size_t) c   *N + q0 + r0 + 8] = o[nb][2]*i1;
        ob[(size_t)(c+1)*N + q0 + r0 + 8] = o[nb][3]*i1;
    }
}

// ---------------- Stage 3: bilinear upsample + residual ----------------
__device__ __forceinline__ float bilin(const float* __restrict__ p, int hp,
                                       int y, int x, float inv_s) {
    float sy = (y + 0.5f)*inv_s - 0.5f;
    float sx = (x + 0.5f)*inv_s - 0.5f;
    float fy = floorf(sy), fx = floorf(sx);
    float wy = sy - fy, wx = sx - fx;
    int y0 = max((int)fy, 0), y1 = min((int)fy + 1, hp-1);
    int x0 = max((int)fx, 0), x1 = min((int)fx + 1, hp-1);
    float a = p[y0*hp + x0], b2 = p[y0*hp + x1];
    float c2 = p[y1*hp + x0], d2 = p[y1*hp + x1];
    return (a*(1.f-wx) + b2*wx)*(1.f-wy) + (c2*(1.f-wx) + d2*wx)*wy;
}

__global__ void __launch_bounds__(256) final_kernel(const float* __restrict__ x,
                                                    float* __restrict__ out) {
    int idx = blockIdx.x*256 + threadIdx.x;
    if (idx >= BB*CC*HH*WW) return;
    int xx = idx & 63, yy = (idx >> 6) & 63, bc = idx >> 12;
    float v = x[idx] + g_o1[idx];
    v += bilin(g_o2 + bc*1024, 32, yy, xx, 0.5f);
    v += bilin(g_o4 + bc*256,  16, yy, xx, 0.25f);
    out[idx] = v;
}

// ---------------- launch ----------------
extern "C" void kernel_launch(void* const* d_in, const int* in_sizes, int n_in,
                              void* d_out, int out_size) {
    const float* x = (const float*)d_in[0];
    const float* w = (const float*)d_in[1];
    float* out = (float*)d_out;

    cudaFuncSetAttribute(attn_fused, cudaFuncAttributeMaxDynamicSharedMemorySize, ATTN_SMEM);

    wtrans_kernel<<<(CC*9*CC + 255)/256, 256>>>(w);
    conv_kernel<<<dim3(16, 8), 512>>>(x);
    poolpack_kernel<<<dim3(84, 8), 256>>>();
    attn_fused<<<dim3(42, 8), 256, ATTN_SMEM>>>();
    final_kernel<<<(BB*CC*HH*WW + 255)/256, 256>>>(x, out);
}